// round 3
// baseline (speedup 1.0000x reference)
#include <cuda_runtime.h>
#include <cuda_bf16.h>
#include <math.h>

// ---------------- problem constants ----------------
#define NB   8
#define NWAY 16
#define NBASE 8000
#define FEAT 512
#define SEM  300
#define MTOT (NB*NBASE)          // 64000
#define INV_TEMP (1.0f/22.62741699796952f)

// ---------------- device scratch (no allocs allowed) ----------------
__device__ float g_h[NB*NBASE*SEM];        // map_sem layer1 (base)
__device__ float g_calib[NB*NBASE*SEM];    // calibrated base_seman
__device__ float g_ktot[NB*NBASE*FEAT];    // fused keys
__device__ float g_v[NB*NBASE*FEAT];       // values
__device__ float g_suph[NB*NWAY*SEM];
__device__ float g_supcalib[NB*NWAY*SEM];
__device__ float g_qtot[NB*NWAY*FEAT];
__device__ float g_meanv[NB*32*FEAT];      // mean partials (vis)
__device__ float g_means[NB*32*SEM];       // mean partials (sem)
__device__ float g_avg[NB*(FEAT+SEM)];
__device__ float g_gv[NB*FEAT];
__device__ float g_gs[NB*SEM];
__device__ float g_attn[NB*NWAY*NBASE];    // softmax probs
__device__ float g_part[NB*25*NWAY*FEAT];  // attn@v split-K partials
__device__ float g_outpre[NB*NWAY*FEAT];
__device__ float g_score_scratch[NB*NWAY*NBASE];
__device__ float g_out_scratch[NB*NWAY*FEAT];

// ---------------- generic tiled GEMM ----------------
// C[M,N] = act(A[M,K] (col-scaled by gate) @ B[K,N] + bias) (+resid) (+=C if accum)
// row-major everywhere; B stored (K,N).
#define BM 64
#define BN 64
#define BK 16
__global__ void gemm_kernel(const float* __restrict__ A, const float* __restrict__ B,
                            const float* __restrict__ bias,
                            const float* __restrict__ gate, int gateK,
                            const float* __restrict__ resid,
                            float* __restrict__ C,
                            int M, int K, int N,
                            long long sAb, long long sBb, long long sCb,
                            int act, int accum)
{
    int b = blockIdx.z;
    A += (long long)b * sAb;
    B += (long long)b * sBb;
    C += (long long)b * sCb;
    const float* gt = gate ? (gate + (long long)b * gateK) : nullptr;

    __shared__ float As[BK][BM+1];
    __shared__ float Bs[BK][BN+1];

    int tid = threadIdx.x;
    int tx = tid & 15, ty = tid >> 4;
    int m0 = blockIdx.y * BM, n0 = blockIdx.x * BN;

    float acc[4][4];
    #pragma unroll
    for (int i = 0; i < 4; i++)
        #pragma unroll
        for (int j = 0; j < 4; j++) acc[i][j] = 0.f;

    for (int k0 = 0; k0 < K; k0 += BK) {
        #pragma unroll
        for (int l = 0; l < 4; l++) {
            int i = tid + l*256;
            int ar = i >> 4, ac = i & 15;
            int gm = m0 + ar, gk = k0 + ac;
            float vv = 0.f;
            if (gm < M && gk < K) {
                vv = A[(long long)gm*K + gk];
                if (gt) vv *= gt[gk];
            }
            As[ac][ar] = vv;
        }
        #pragma unroll
        for (int l = 0; l < 4; l++) {
            int i = tid + l*256;
            int br = i >> 6, bc = i & 63;
            int gk = k0 + br, gn = n0 + bc;
            Bs[br][bc] = (gk < K && gn < N) ? B[(long long)gk*N + gn] : 0.f;
        }
        __syncthreads();
        #pragma unroll
        for (int kk = 0; kk < BK; kk++) {
            float a[4], bb[4];
            #pragma unroll
            for (int i = 0; i < 4; i++) a[i] = As[kk][ty*4+i];
            #pragma unroll
            for (int j = 0; j < 4; j++) bb[j] = Bs[kk][tx*4+j];
            #pragma unroll
            for (int i = 0; i < 4; i++)
                #pragma unroll
                for (int j = 0; j < 4; j++)
                    acc[i][j] += a[i]*bb[j];
        }
        __syncthreads();
    }

    #pragma unroll
    for (int i = 0; i < 4; i++) {
        int gm = m0 + ty*4 + i;
        if (gm >= M) continue;
        #pragma unroll
        for (int j = 0; j < 4; j++) {
            int gn = n0 + tx*4 + j;
            if (gn >= N) continue;
            float vv = acc[i][j];
            if (bias) vv += bias[gn];
            if (act == 1) vv = (vv >= 0.f) ? vv : 0.1f*vv;   // LeakyReLU(0.1)
            if (resid) vv += resid[(long long)gm*N + gn];
            long long idx = (long long)gm*N + gn;
            if (accum) vv += C[idx];
            C[idx] = vv;
        }
    }
}

// ---------------- column means (partial over 250-row chunks) ----------------
__global__ void mean_part_kernel(const float* __restrict__ X, float* __restrict__ part, int C)
{
    int b = blockIdx.y, ch = blockIdx.x;       // 32 chunks of 250 rows
    int c = threadIdx.x;
    if (c >= C) return;
    const float* p = X + ((long long)b*NBASE + ch*250)*C + c;
    float s = 0.f;
    for (int r = 0; r < 250; r++) s += p[(long long)r*C];
    part[((long long)b*32 + ch)*C + c] = s;
}

__global__ void avg_kernel(const float* __restrict__ pv, const float* __restrict__ ps,
                           float* __restrict__ avg)
{
    int b = blockIdx.x, c = threadIdx.x;       // 1024 threads
    if (c < FEAT) {
        float s = 0.f;
        for (int ch = 0; ch < 32; ch++) s += pv[((long long)b*32+ch)*FEAT + c];
        avg[b*(FEAT+SEM) + c] = s * (1.0f/NBASE);
    } else if (c < FEAT + SEM) {
        int cc = c - FEAT;
        float s = 0.f;
        for (int ch = 0; ch < 32; ch++) s += ps[((long long)b*32+ch)*SEM + cc];
        avg[b*(FEAT+SEM) + FEAT + cc] = s * (1.0f/NBASE);
    }
}

// gate[b][j] = 1 + sigmoid(avg[b]·W[:,j] + bias[j]);  W is (812, N) row-major
__global__ void gate_kernel(const float* __restrict__ avg, const float* __restrict__ W,
                            const float* __restrict__ bias, float* __restrict__ gate, int N)
{
    int b = blockIdx.x, j = threadIdx.x;
    __shared__ float av[FEAT+SEM];
    for (int i = threadIdx.x; i < FEAT+SEM; i += blockDim.x) av[i] = avg[b*(FEAT+SEM) + i];
    __syncthreads();
    if (j < N) {
        float s = bias[j];
        for (int k = 0; k < FEAT+SEM; k++) s += av[k]*W[(long long)k*N + j];
        gate[b*N + j] = 1.f + 1.f/(1.f + expf(-s));
    }
}

// ---------------- attention scores: score[b,w,n] = (q_tot[b,w]·k_tot[b,n]) / TEMP ----
__global__ void attn_kernel(const float* __restrict__ ktot, const float* __restrict__ qtot,
                            float* __restrict__ score)
{
    int b = blockIdx.y;
    int n0 = blockIdx.x * 32;
    __shared__ float qs[NWAY][FEAT];
    __shared__ float ks[32][33];
    const float* q = qtot + (long long)b*NWAY*FEAT;
    for (int i = threadIdx.x; i < NWAY*FEAT; i += 256) qs[i>>9][i&511] = q[i];
    int r  = threadIdx.x & 31;   // base row within tile
    int wg = threadIdx.x >> 5;   // 0..7  → ways 2*wg, 2*wg+1
    float acc0 = 0.f, acc1 = 0.f;
    const float* kb = ktot + ((long long)b*NBASE + n0)*FEAT;
    for (int k0 = 0; k0 < FEAT; k0 += 32) {
        __syncthreads();
        for (int i = threadIdx.x; i < 32*32; i += 256) {
            int rr = i >> 5, cc = i & 31;
            ks[rr][cc] = kb[(long long)rr*FEAT + k0 + cc];
        }
        __syncthreads();
        #pragma unroll
        for (int kk = 0; kk < 32; kk++) {
            float kv = ks[r][kk];
            acc0 += kv * qs[2*wg  ][k0+kk];
            acc1 += kv * qs[2*wg+1][k0+kk];
        }
    }
    score[((long long)b*NWAY + 2*wg  )*NBASE + n0 + r] = acc0 * INV_TEMP;
    score[((long long)b*NWAY + 2*wg+1)*NBASE + n0 + r] = acc1 * INV_TEMP;
}

// ---------------- softmax over 8000 per (b,w) row ----------------
__global__ void softmax_kernel(const float* __restrict__ score, float* __restrict__ attn)
{
    int row = blockIdx.x;                    // 0..127
    const float* s = score + (long long)row*NBASE;
    float* a = attn + (long long)row*NBASE;
    __shared__ float red[256];
    float mx = -1e30f;
    for (int i = threadIdx.x; i < NBASE; i += 256) mx = fmaxf(mx, s[i]);
    red[threadIdx.x] = mx; __syncthreads();
    for (int st = 128; st > 0; st >>= 1) {
        if (threadIdx.x < st) red[threadIdx.x] = fmaxf(red[threadIdx.x], red[threadIdx.x+st]);
        __syncthreads();
    }
    mx = red[0]; __syncthreads();
    float sum = 0.f;
    for (int i = threadIdx.x; i < NBASE; i += 256) {
        float e = expf(s[i] - mx);
        a[i] = e;
        sum += e;
    }
    red[threadIdx.x] = sum; __syncthreads();
    for (int st = 128; st > 0; st >>= 1) {
        if (threadIdx.x < st) red[threadIdx.x] += red[threadIdx.x+st];
        __syncthreads();
    }
    float inv = 1.f/red[0];
    for (int i = threadIdx.x; i < NBASE; i += 256) a[i] *= inv;
}

// ---------------- attn @ v, deterministic split-K: 25 chunks of 320 rows -----
__global__ void av_partial_kernel(const float* __restrict__ attn, const float* __restrict__ v,
                                  float* __restrict__ part)
{
    int b  = blockIdx.x;     // 8
    int ch = blockIdx.y;     // 25
    int n0 = ch * 320;
    __shared__ float as[NWAY][32];
    int c0 = threadIdx.x;    // cols c0 and c0+256
    float acc[NWAY][2];
    #pragma unroll
    for (int w = 0; w < NWAY; w++) { acc[w][0] = 0.f; acc[w][1] = 0.f; }

    for (int nb = 0; nb < 320; nb += 32) {
        __syncthreads();
        for (int i = threadIdx.x; i < NWAY*32; i += 256) {
            int w = i >> 5, nn = i & 31;
            as[w][nn] = attn[((long long)b*NWAY + w)*NBASE + n0 + nb + nn];
        }
        __syncthreads();
        for (int nn = 0; nn < 32; nn++) {
            const float* vr = v + ((long long)b*NBASE + n0 + nb + nn)*FEAT;
            float v0 = vr[c0], v1 = vr[c0+256];
            #pragma unroll
            for (int w = 0; w < NWAY; w++) {
                acc[w][0] += as[w][nn]*v0;
                acc[w][1] += as[w][nn]*v1;
            }
        }
    }
    #pragma unroll
    for (int w = 0; w < NWAY; w++) {
        part[(((long long)b*25 + ch)*NWAY + w)*FEAT + c0      ] = acc[w][0];
        part[(((long long)b*25 + ch)*NWAY + w)*FEAT + c0 + 256] = acc[w][1];
    }
}

__global__ void av_reduce_kernel(const float* __restrict__ part, float* __restrict__ outpre)
{
    long long i = (long long)blockIdx.x*256 + threadIdx.x;   // 65536 total
    int c = i & 511;
    long long bw = i >> 9;
    int w = bw & 15;
    int b = (int)(bw >> 4);
    float s = 0.f;
    for (int ch = 0; ch < 25; ch++)
        s += part[(((long long)b*25 + ch)*NWAY + w)*FEAT + c];
    outpre[i] = s;
}

// ---------------- host ----------------
extern "C" void kernel_launch(void* const* d_in, const int* in_sizes, int n_in,
                              void* d_out, int out_size)
{
    const float* support_feat  = (const float*)d_in[0];
    const float* base_weights  = (const float*)d_in[1];
    const float* support_seman = (const float*)d_in[2];
    const float* base_seman    = (const float*)d_in[3];
    const float* map_w1 = (const float*)d_in[4];
    const float* map_b1 = (const float*)d_in[5];
    const float* map_w2 = (const float*)d_in[6];
    const float* map_b2 = (const float*)d_in[7];
    const float* visfuse_w = (const float*)d_in[8];
    const float* visfuse_b = (const float*)d_in[9];
    const float* semfuse_w = (const float*)d_in[10];
    const float* semfuse_b = (const float*)d_in[11];
    const float* w_qs = (const float*)d_in[12];
    const float* w_ks = (const float*)d_in[13];
    const float* w_vs = (const float*)d_in[14];
    const float* w_qs_sem = (const float*)d_in[15];
    const float* w_ks_sem = (const float*)d_in[16];
    const float* fc_w = (const float*)d_in[17];

    float *h, *calib, *ktot, *v, *suph, *supcalib, *qtot;
    float *meanv, *means, *avg, *gv, *gs, *attn, *part, *outpre, *score_sc, *out_sc;
    cudaGetSymbolAddress((void**)&h, g_h);
    cudaGetSymbolAddress((void**)&calib, g_calib);
    cudaGetSymbolAddress((void**)&ktot, g_ktot);
    cudaGetSymbolAddress((void**)&v, g_v);
    cudaGetSymbolAddress((void**)&suph, g_suph);
    cudaGetSymbolAddress((void**)&supcalib, g_supcalib);
    cudaGetSymbolAddress((void**)&qtot, g_qtot);
    cudaGetSymbolAddress((void**)&meanv, g_meanv);
    cudaGetSymbolAddress((void**)&means, g_means);
    cudaGetSymbolAddress((void**)&avg, g_avg);
    cudaGetSymbolAddress((void**)&gv, g_gv);
    cudaGetSymbolAddress((void**)&gs, g_gs);
    cudaGetSymbolAddress((void**)&attn, g_attn);
    cudaGetSymbolAddress((void**)&part, g_part);
    cudaGetSymbolAddress((void**)&outpre, g_outpre);
    cudaGetSymbolAddress((void**)&score_sc, g_score_scratch);
    cudaGetSymbolAddress((void**)&out_sc, g_out_scratch);

    // output layout handling: reference returns (out, attn_score)
    const int OUT_N = NB*NWAY*FEAT;            // 65536
    const int SC_N  = NB*NWAY*NBASE;           // 1024000
    float* out_ptr   = (float*)d_out;
    float* score_ptr = score_sc;
    if (out_size >= OUT_N + SC_N) {            // both, out first
        out_ptr = (float*)d_out;
        score_ptr = (float*)d_out + OUT_N;
    } else if (out_size == SC_N) {             // only attn_score
        out_ptr = out_sc;
        score_ptr = (float*)d_out;
    } // else: only out → score to scratch (defaults above)

    // 1) map_sem on base semantics: h = lrelu(base_seman@w1+b1); calib = h@w2+b2
    gemm_kernel<<<dim3(5, 1000, 1), 256>>>(base_seman, map_w1, map_b1, nullptr, 0, nullptr,
                                           h, MTOT, SEM, SEM, 0, 0, 0, 1, 0);
    gemm_kernel<<<dim3(5, 1000, 1), 256>>>(h, map_w2, map_b2, nullptr, 0, nullptr,
                                           calib, MTOT, SEM, SEM, 0, 0, 0, 0, 0);

    // 2) map_sem on support semantics (tiny)
    gemm_kernel<<<dim3(5, 2, 1), 256>>>(support_seman, map_w1, map_b1, nullptr, 0, nullptr,
                                        suph, NB*NWAY, SEM, SEM, 0, 0, 0, 1, 0);
    gemm_kernel<<<dim3(5, 2, 1), 256>>>(suph, map_w2, map_b2, nullptr, 0, nullptr,
                                        supcalib, NB*NWAY, SEM, SEM, 0, 0, 0, 0, 0);

    // 3) means over base classes → avg → gates
    mean_part_kernel<<<dim3(32, NB), 512>>>(base_weights, meanv, FEAT);
    mean_part_kernel<<<dim3(32, NB), 512>>>(calib, means, SEM);
    avg_kernel<<<NB, 1024>>>(meanv, means, avg);
    gate_kernel<<<NB, 512>>>(avg, visfuse_w, visfuse_b, gv, FEAT);
    gate_kernel<<<NB, 512>>>(avg, semfuse_w, semfuse_b, gs, SEM);

    // 4) k_tot = (base_weights ⊙ gate_vis)@w_ks + (calib ⊙ gate_sem)@w_ks_sem   (batched, gate fused into A-load)
    gemm_kernel<<<dim3(8, 125, NB), 256>>>(base_weights, w_ks, nullptr, gv, FEAT, nullptr,
                                           ktot, NBASE, FEAT, FEAT,
                                           (long long)NBASE*FEAT, 0, (long long)NBASE*FEAT, 0, 0);
    gemm_kernel<<<dim3(8, 125, NB), 256>>>(calib, w_ks_sem, nullptr, gs, SEM, nullptr,
                                           ktot, NBASE, SEM, FEAT,
                                           (long long)NBASE*SEM, 0, (long long)NBASE*FEAT, 0, 1);

    // 5) v = base_weights @ w_vs (flattened over batch)
    gemm_kernel<<<dim3(8, 1000, 1), 256>>>(base_weights, w_vs, nullptr, nullptr, 0, nullptr,
                                           v, MTOT, FEAT, FEAT, 0, 0, 0, 0, 0);

    // 6) q_tot = support_feat@w_qs + supcalib@w_qs_sem
    gemm_kernel<<<dim3(8, 2, 1), 256>>>(support_feat, w_qs, nullptr, nullptr, 0, nullptr,
                                        qtot, NB*NWAY, FEAT, FEAT, 0, 0, 0, 0, 0);
    gemm_kernel<<<dim3(8, 2, 1), 256>>>(supcalib, w_qs_sem, nullptr, nullptr, 0, nullptr,
                                        qtot, NB*NWAY, SEM, FEAT, 0, 0, 0, 0, 1);

    // 7) scores (written straight to output region), softmax, attn@v, final proj + residual
    attn_kernel<<<dim3(NBASE/32, NB), 256>>>(ktot, qtot, score_ptr);
    softmax_kernel<<<NB*NWAY, 256>>>(score_ptr, attn);
    av_partial_kernel<<<dim3(NB, 25), 256>>>(attn, v, part);
    av_reduce_kernel<<<256, 256>>>(part, outpre);
    gemm_kernel<<<dim3(8, 2, 1), 256>>>(outpre, fc_w, nullptr, nullptr, 0, support_feat,
                                        out_ptr, NB*NWAY, FEAT, FEAT, 0, 0, 0, 0, 0);
}

// round 5
// speedup vs baseline: 1.5577x; 1.5577x over previous
#include <cuda_runtime.h>
#include <cuda_bf16.h>
#include <mma.h>
#include <math.h>
#include <stdint.h>

using namespace nvcuda;

// ---------------- problem constants ----------------
#define NB   8
#define NWAY 16
#define NBASE 8000
#define FEAT 512
#define SEM  300
#define MTOT (NB*NBASE)          // 64000
#define INV_TEMP (1.0f/22.62741699796952f)

// ---------------- device scratch (no allocs allowed) ----------------
__device__ float g_h[NB*NBASE*SEM];        // map_sem layer1 (base)
__device__ float g_calib[NB*NBASE*SEM];    // calibrated base_seman
__device__ float g_ktot[NB*NBASE*FEAT];    // fused keys
__device__ float g_v[NB*NBASE*FEAT];       // values
__device__ float g_suph[NB*NWAY*SEM];
__device__ float g_supcalib[NB*NWAY*SEM];
__device__ float g_qtot[NB*NWAY*FEAT];
__device__ float g_meanv[NB*32*FEAT];
__device__ float g_means[NB*32*SEM];
__device__ float g_avg[NB*(FEAT+SEM)];
__device__ float g_gv[NB*FEAT];
__device__ float g_gs[NB*SEM];
__device__ float g_attn[NB*NWAY*NBASE];
__device__ float g_part[NB*25*NWAY*FEAT];
__device__ float g_outpre[NB*NWAY*FEAT];
__device__ float g_score_scratch[NB*NWAY*NBASE];
__device__ float g_out_scratch[NB*NWAY*FEAT];

// pre-split / pre-transposed weights, bf16 hi/lo, layout [n, kpad]
__device__ __nv_bfloat16 g_wks_h[512*512],  g_wks_l[512*512];
__device__ __nv_bfloat16 g_wvs_h[512*512],  g_wvs_l[512*512];
__device__ __nv_bfloat16 g_wkss_h[512*320], g_wkss_l[512*320];
__device__ __nv_bfloat16 g_w1_h[384*320],   g_w1_l[384*320];
__device__ __nv_bfloat16 g_w2_h[384*320],   g_w2_l[384*320];

__device__ __forceinline__ uint32_t bf16pack(float a, float b) {
    __nv_bfloat162 t = __floats2bfloat162_rn(a, b);
    return *reinterpret_cast<uint32_t*>(&t);
}

// ================= weight prep: transpose + bf16 hi/lo split =================
// W stored (K,N) row-major -> Th/Tl stored [n, Kp] (transposed, zero-padded)
__global__ void split_w_kernel(const float* __restrict__ W, int K, int N,
                               __nv_bfloat16* __restrict__ Th, __nv_bfloat16* __restrict__ Tl,
                               int Kp, int Nr)
{
    long long i = (long long)blockIdx.x*256 + threadIdx.x;
    if (i >= (long long)Nr*Kp) return;
    int n = (int)(i / Kp), k = (int)(i % Kp);
    float v = (k < K && n < N) ? W[(long long)k*N + n] : 0.f;
    __nv_bfloat16 h = __float2bfloat16(v);
    Th[i] = h;
    Tl[i] = __float2bfloat16(v - __bfloat162float(h));
}

// ================= WMMA bf16x3 GEMM =================
// C[b][m,n] = act( (A[b][m,:] .* gate[b]) @ Wt^T + bias ) (+= if accum)
// A fp32 [Mrows, K]; Wt pre-split bf16 [n, Kp] (i.e., B col-major KxN); C fp32 (row stride Nc).
// Block tile 128x128, 8 warps (4m x 2n), warp tile 32x64, K-chunk 32.
#define LDT 40     // smem tile leading dim in bf16 (32 + 8 pad, 80B rows)
#define LDC 136    // smem epilogue leading dim in f32
__global__ void __launch_bounds__(256) wmma_gemm(
    const float* __restrict__ A,
    const __nv_bfloat16* __restrict__ Bh, const __nv_bfloat16* __restrict__ Bl,
    int Mrows, int K, int Kp, int N, int Nc,
    long long sAb, long long sCb,
    const float* __restrict__ bias,
    const float* __restrict__ gate, int gateLen,
    float* __restrict__ C, int act, int accum)
{
    extern __shared__ char smem[];
    __nv_bfloat16* sAh = (__nv_bfloat16*)smem;
    __nv_bfloat16* sAl = sAh + 128*LDT;
    __nv_bfloat16* sBh = sAl + 128*LDT;
    __nv_bfloat16* sBl = sBh + 128*LDT;
    float* sC = (float*)smem;                 // reused after final sync

    int b = blockIdx.z;
    const float* Ab = A + (long long)b*sAb;
    float* Cb = C + (long long)b*sCb;
    const float* gt = gate ? gate + (long long)b*gateLen : nullptr;
    int m0 = blockIdx.y*128, n0 = blockIdx.x*128;
    int tid = threadIdx.x, wid = tid >> 5;
    int wm = (wid & 3)*32, wn = (wid >> 2)*64;

    wmma::fragment<wmma::accumulator, 16, 16, 16, float> acc[2][4];
    #pragma unroll
    for (int i = 0; i < 2; i++)
        #pragma unroll
        for (int j = 0; j < 4; j++) wmma::fill_fragment(acc[i][j], 0.f);

    for (int k0 = 0; k0 < Kp; k0 += 32) {
        __syncthreads();   // previous chunk's compute must finish before overwrite
        // ---- A: fp32 load + gate + hi/lo split -> smem ----
        #pragma unroll
        for (int j = 0; j < 4; j++) {
            int lin = tid + j*256;            // float4 units; 1024 = 128 rows x 8
            int row = lin >> 3, c4 = lin & 7;
            int gm = m0 + row, kk = k0 + c4*4;
            float4 v = make_float4(0.f, 0.f, 0.f, 0.f);
            if (gm < Mrows && kk < K) {
                v = *reinterpret_cast<const float4*>(Ab + (long long)gm*K + kk);
                if (gt) { v.x *= gt[kk]; v.y *= gt[kk+1]; v.z *= gt[kk+2]; v.w *= gt[kk+3]; }
            }
            float h0 = __bfloat162float(__float2bfloat16(v.x));
            float h1 = __bfloat162float(__float2bfloat16(v.y));
            float h2 = __bfloat162float(__float2bfloat16(v.z));
            float h3 = __bfloat162float(__float2bfloat16(v.w));
            uint32_t* dh = (uint32_t*)&sAh[row*LDT + c4*4];
            uint32_t* dl = (uint32_t*)&sAl[row*LDT + c4*4];
            dh[0] = bf16pack(h0, h1);          dh[1] = bf16pack(h2, h3);
            dl[0] = bf16pack(v.x-h0, v.y-h1);  dl[1] = bf16pack(v.z-h2, v.w-h3);
        }
        // ---- B: pre-split bf16 -> smem ([n][k], 32 bf16 per row = 4 uint4) ----
        #pragma unroll
        for (int j = 0; j < 2; j++) {
            int lin = tid + j*256;            // uint4 units; 512 = 128 rows x 4
            int n = lin >> 2, q = lin & 3;
            const uint4* srch = (const uint4*)(Bh + (long long)(n0+n)*Kp + k0) + q;
            const uint4* srcl = (const uint4*)(Bl + (long long)(n0+n)*Kp + k0) + q;
            *(uint4*)&sBh[n*LDT + q*8] = *srch;
            *(uint4*)&sBl[n*LDT + q*8] = *srcl;
        }
        __syncthreads();
        // ---- compute: 2 k-substeps of 16, bf16x3 (hh + hl + lh) ----
        #pragma unroll
        for (int ks = 0; ks < 2; ks++) {
            wmma::fragment<wmma::matrix_a, 16, 16, 16, __nv_bfloat16, wmma::row_major> ah[2], al[2];
            wmma::fragment<wmma::matrix_b, 16, 16, 16, __nv_bfloat16, wmma::col_major> bh[4], bl[4];
            #pragma unroll
            for (int i = 0; i < 2; i++) {
                wmma::load_matrix_sync(ah[i], &sAh[(wm + i*16)*LDT + ks*16], LDT);
                wmma::load_matrix_sync(al[i], &sAl[(wm + i*16)*LDT + ks*16], LDT);
            }
            #pragma unroll
            for (int j = 0; j < 4; j++) {
                wmma::load_matrix_sync(bh[j], &sBh[(wn + j*16)*LDT + ks*16], LDT);
                wmma::load_matrix_sync(bl[j], &sBl[(wn + j*16)*LDT + ks*16], LDT);
            }
            #pragma unroll
            for (int i = 0; i < 2; i++)
                #pragma unroll
                for (int j = 0; j < 4; j++) {
                    wmma::mma_sync(acc[i][j], ah[i], bh[j], acc[i][j]);
                    wmma::mma_sync(acc[i][j], ah[i], bl[j], acc[i][j]);
                    wmma::mma_sync(acc[i][j], al[i], bh[j], acc[i][j]);
                }
        }
    }
    __syncthreads();
    // ---- epilogue: frags -> smem -> gmem with bias/act/accum ----
    #pragma unroll
    for (int i = 0; i < 2; i++)
        #pragma unroll
        for (int j = 0; j < 4; j++)
            wmma::store_matrix_sync(&sC[(wm + i*16)*LDC + wn + j*16], acc[i][j], LDC,
                                    wmma::mem_row_major);
    __syncthreads();
    for (int j = 0; j < 64; j++) {
        int lin = tid + j*256;                // 16384 = 128x128
        int row = lin >> 7, col = lin & 127;
        int gm = m0 + row, gn = n0 + col;
        if (gm < Mrows && gn < N) {
            float v = sC[row*LDC + col];
            if (bias) v += bias[gn];
            if (act)  v = (v >= 0.f) ? v : 0.1f*v;
            long long idx = (long long)gm*Nc + gn;
            if (accum) v += Cb[idx];
            Cb[idx] = v;
        }
    }
}

// ---------------- fp32 tiled GEMM (small matrices only) ----------------
#define BM 64
#define BN 64
#define BK 16
__global__ void gemm_kernel(const float* __restrict__ A, const float* __restrict__ B,
                            const float* __restrict__ bias,
                            const float* __restrict__ gate, int gateK,
                            const float* __restrict__ resid,
                            float* __restrict__ C,
                            int M, int K, int N,
                            long long sAb, long long sBb, long long sCb,
                            int act, int accum)
{
    int b = blockIdx.z;
    A += (long long)b * sAb;
    B += (long long)b * sBb;
    C += (long long)b * sCb;
    const float* gt = gate ? (gate + (long long)b * gateK) : nullptr;

    __shared__ float As[BK][BM+1];
    __shared__ float Bs[BK][BN+1];

    int tid = threadIdx.x;
    int tx = tid & 15, ty = tid >> 4;
    int m0 = blockIdx.y * BM, n0 = blockIdx.x * BN;

    float acc[4][4];
    #pragma unroll
    for (int i = 0; i < 4; i++)
        #pragma unroll
        for (int j = 0; j < 4; j++) acc[i][j] = 0.f;

    for (int k0 = 0; k0 < K; k0 += BK) {
        #pragma unroll
        for (int l = 0; l < 4; l++) {
            int i = tid + l*256;
            int ar = i >> 4, ac = i & 15;
            int gm = m0 + ar, gk = k0 + ac;
            float vv = 0.f;
            if (gm < M && gk < K) {
                vv = A[(long long)gm*K + gk];
                if (gt) vv *= gt[gk];
            }
            As[ac][ar] = vv;
        }
        #pragma unroll
        for (int l = 0; l < 4; l++) {
            int i = tid + l*256;
            int br = i >> 6, bc = i & 63;
            int gk = k0 + br, gn = n0 + bc;
            Bs[br][bc] = (gk < K && gn < N) ? B[(long long)gk*N + gn] : 0.f;
        }
        __syncthreads();
        #pragma unroll
        for (int kk = 0; kk < BK; kk++) {
            float a[4], bb[4];
            #pragma unroll
            for (int i = 0; i < 4; i++) a[i] = As[kk][ty*4+i];
            #pragma unroll
            for (int j = 0; j < 4; j++) bb[j] = Bs[kk][tx*4+j];
            #pragma unroll
            for (int i = 0; i < 4; i++)
                #pragma unroll
                for (int j = 0; j < 4; j++)
                    acc[i][j] += a[i]*bb[j];
        }
        __syncthreads();
    }

    #pragma unroll
    for (int i = 0; i < 4; i++) {
        int gm = m0 + ty*4 + i;
        if (gm >= M) continue;
        #pragma unroll
        for (int j = 0; j < 4; j++) {
            int gn = n0 + tx*4 + j;
            if (gn >= N) continue;
            float vv = acc[i][j];
            if (bias) vv += bias[gn];
            if (act == 1) vv = (vv >= 0.f) ? vv : 0.1f*vv;
            if (resid) vv += resid[(long long)gm*N + gn];
            long long idx = (long long)gm*N + gn;
            if (accum) vv += C[idx];
            C[idx] = vv;
        }
    }
}

// ---------------- column means (partial over 250-row chunks) ----------------
__global__ void mean_part_kernel(const float* __restrict__ X, float* __restrict__ part, int C)
{
    int b = blockIdx.y, ch = blockIdx.x;
    int c = threadIdx.x;
    if (c >= C) return;
    const float* p = X + ((long long)b*NBASE + ch*250)*C + c;
    float s = 0.f;
    for (int r = 0; r < 250; r++) s += p[(long long)r*C];
    part[((long long)b*32 + ch)*C + c] = s;
}

__global__ void avg_kernel(const float* __restrict__ pv, const float* __restrict__ ps,
                           float* __restrict__ avg)
{
    int b = blockIdx.x, c = threadIdx.x;
    if (c < FEAT) {
        float s = 0.f;
        for (int ch = 0; ch < 32; ch++) s += pv[((long long)b*32+ch)*FEAT + c];
        avg[b*(FEAT+SEM) + c] = s * (1.0f/NBASE);
    } else if (c < FEAT + SEM) {
        int cc = c - FEAT;
        float s = 0.f;
        for (int ch = 0; ch < 32; ch++) s += ps[((long long)b*32+ch)*SEM + cc];
        avg[b*(FEAT+SEM) + FEAT + cc] = s * (1.0f/NBASE);
    }
}

__global__ void gate_kernel(const float* __restrict__ avg, const float* __restrict__ W,
                            const float* __restrict__ bias, float* __restrict__ gate, int N)
{
    int b = blockIdx.x, j = threadIdx.x;
    __shared__ float av[FEAT+SEM];
    for (int i = threadIdx.x; i < FEAT+SEM; i += blockDim.x) av[i] = avg[b*(FEAT+SEM) + i];
    __syncthreads();
    if (j < N) {
        float s = bias[j];
        for (int k = 0; k < FEAT+SEM; k++) s += av[k]*W[(long long)k*N + j];
        gate[b*N + j] = 1.f + 1.f/(1.f + expf(-s));
    }
}

// ---------------- attention scores ----------------
__global__ void attn_kernel(const float* __restrict__ ktot, const float* __restrict__ qtot,
                            float* __restrict__ score)
{
    int b = blockIdx.y;
    int n0 = blockIdx.x * 32;
    __shared__ float qs[NWAY][FEAT];
    __shared__ float ks[32][33];
    const float* q = qtot + (long long)b*NWAY*FEAT;
    for (int i = threadIdx.x; i < NWAY*FEAT; i += 256) qs[i>>9][i&511] = q[i];
    int r  = threadIdx.x & 31;
    int wg = threadIdx.x >> 5;
    float acc0 = 0.f, acc1 = 0.f;
    const float* kb = ktot + ((long long)b*NBASE + n0)*FEAT;
    for (int k0 = 0; k0 < FEAT; k0 += 32) {
        __syncthreads();
        for (int i = threadIdx.x; i < 32*32; i += 256) {
            int rr = i >> 5, cc = i & 31;
            ks[rr][cc] = kb[(long long)rr*FEAT + k0 + cc];
        }
        __syncthreads();
        #pragma unroll
        for (int kk = 0; kk < 32; kk++) {
            float kv = ks[r][kk];
            acc0 += kv * qs[2*wg  ][k0+kk];
            acc1 += kv * qs[2*wg+1][k0+kk];
        }
    }
    score[((long long)b*NWAY + 2*wg  )*NBASE + n0 + r] = acc0 * INV_TEMP;
    score[((long long)b*NWAY + 2*wg+1)*NBASE + n0 + r] = acc1 * INV_TEMP;
}

// ---------------- softmax ----------------
__global__ void softmax_kernel(const float* __restrict__ score, float* __restrict__ attn)
{
    int row = blockIdx.x;
    const float* s = score + (long long)row*NBASE;
    float* a = attn + (long long)row*NBASE;
    __shared__ float red[256];
    float mx = -1e30f;
    for (int i = threadIdx.x; i < NBASE; i += 256) mx = fmaxf(mx, s[i]);
    red[threadIdx.x] = mx; __syncthreads();
    for (int st = 128; st > 0; st >>= 1) {
        if (threadIdx.x < st) red[threadIdx.x] = fmaxf(red[threadIdx.x], red[threadIdx.x+st]);
        __syncthreads();
    }
    mx = red[0]; __syncthreads();
    float sum = 0.f;
    for (int i = threadIdx.x; i < NBASE; i += 256) {
        float e = expf(s[i] - mx);
        a[i] = e;
        sum += e;
    }
    red[threadIdx.x] = sum; __syncthreads();
    for (int st = 128; st > 0; st >>= 1) {
        if (threadIdx.x < st) red[threadIdx.x] += red[threadIdx.x+st];
        __syncthreads();
    }
    float inv = 1.f/red[0];
    for (int i = threadIdx.x; i < NBASE; i += 256) a[i] *= inv;
}

// ---------------- attn @ v, deterministic split-K ----------------
__global__ void av_partial_kernel(const float* __restrict__ attn, const float* __restrict__ v,
                                  float* __restrict__ part)
{
    int b  = blockIdx.x;
    int ch = blockIdx.y;
    int n0 = ch * 320;
    __shared__ float as[NWAY][32];
    int c0 = threadIdx.x;
    float acc[NWAY][2];
    #pragma unroll
    for (int w = 0; w < NWAY; w++) { acc[w][0] = 0.f; acc[w][1] = 0.f; }

    for (int nb = 0; nb < 320; nb += 32) {
        __syncthreads();
        for (int i = threadIdx.x; i < NWAY*32; i += 256) {
            int w = i >> 5, nn = i & 31;
            as[w][nn] = attn[((long long)b*NWAY + w)*NBASE + n0 + nb + nn];
        }
        __syncthreads();
        for (int nn = 0; nn < 32; nn++) {
            const float* vr = v + ((long long)b*NBASE + n0 + nb + nn)*FEAT;
            float v0 = vr[c0], v1 = vr[c0+256];
            #pragma unroll
            for (int w = 0; w < NWAY; w++) {
                acc[w][0] += as[w][nn]*v0;
                acc[w][1] += as[w][nn]*v1;
            }
        }
    }
    #pragma unroll
    for (int w = 0; w < NWAY; w++) {
        part[(((long long)b*25 + ch)*NWAY + w)*FEAT + c0      ] = acc[w][0];
        part[(((long long)b*25 + ch)*NWAY + w)*FEAT + c0 + 256] = acc[w][1];
    }
}

__global__ void av_reduce_kernel(const float* __restrict__ part, float* __restrict__ outpre)
{
    long long i = (long long)blockIdx.x*256 + threadIdx.x;
    int c = i & 511;
    long long bw = i >> 9;
    int w = bw & 15;
    int b = (int)(bw >> 4);
    float s = 0.f;
    for (int ch = 0; ch < 25; ch++)
        s += part[(((long long)b*25 + ch)*NWAY + w)*FEAT + c];
    outpre[i] = s;
}

// ---------------- host ----------------
extern "C" void kernel_launch(void* const* d_in, const int* in_sizes, int n_in,
                              void* d_out, int out_size)
{
    const float* support_feat  = (const float*)d_in[0];
    const float* base_weights  = (const float*)d_in[1];
    const float* support_seman = (const float*)d_in[2];
    const float* base_seman    = (const float*)d_in[3];
    const float* map_w1 = (const float*)d_in[4];
    const float* map_b1 = (const float*)d_in[5];
    const float* map_w2 = (const float*)d_in[6];
    const float* map_b2 = (const float*)d_in[7];
    const float* visfuse_w = (const float*)d_in[8];
    const float* visfuse_b = (const float*)d_in[9];
    const float* semfuse_w = (const float*)d_in[10];
    const float* semfuse_b = (const float*)d_in[11];
    const float* w_qs = (const float*)d_in[12];
    const float* w_ks = (const float*)d_in[13];
    const float* w_vs = (const float*)d_in[14];
    const float* w_qs_sem = (const float*)d_in[15];
    const float* w_ks_sem = (const float*)d_in[16];
    const float* fc_w = (const float*)d_in[17];

    float *h, *calib, *ktot, *v, *suph, *supcalib, *qtot;
    float *meanv, *means, *avg, *gv, *gs, *attn, *part, *outpre, *score_sc, *out_sc;
    cudaGetSymbolAddress((void**)&h, g_h);
    cudaGetSymbolAddress((void**)&calib, g_calib);
    cudaGetSymbolAddress((void**)&ktot, g_ktot);
    cudaGetSymbolAddress((void**)&v, g_v);
    cudaGetSymbolAddress((void**)&suph, g_suph);
    cudaGetSymbolAddress((void**)&supcalib, g_supcalib);
    cudaGetSymbolAddress((void**)&qtot, g_qtot);
    cudaGetSymbolAddress((void**)&meanv, g_meanv);
    cudaGetSymbolAddress((void**)&means, g_means);
    cudaGetSymbolAddress((void**)&avg, g_avg);
    cudaGetSymbolAddress((void**)&gv, g_gv);
    cudaGetSymbolAddress((void**)&gs, g_gs);
    cudaGetSymbolAddress((void**)&attn, g_attn);
    cudaGetSymbolAddress((void**)&part, g_part);
    cudaGetSymbolAddress((void**)&outpre, g_outpre);
    cudaGetSymbolAddress((void**)&score_sc, g_score_scratch);
    cudaGetSymbolAddress((void**)&out_sc, g_out_scratch);

    __nv_bfloat16 *wksh, *wksl, *wvsh, *wvsl, *wkssh, *wkssl, *w1h, *w1l, *w2h, *w2l;
    cudaGetSymbolAddress((void**)&wksh, g_wks_h);  cudaGetSymbolAddress((void**)&wksl, g_wks_l);
    cudaGetSymbolAddress((void**)&wvsh, g_wvs_h);  cudaGetSymbolAddress((void**)&wvsl, g_wvs_l);
    cudaGetSymbolAddress((void**)&wkssh, g_wkss_h); cudaGetSymbolAddress((void**)&wkssl, g_wkss_l);
    cudaGetSymbolAddress((void**)&w1h, g_w1_h);    cudaGetSymbolAddress((void**)&w1l, g_w1_l);
    cudaGetSymbolAddress((void**)&w2h, g_w2_h);    cudaGetSymbolAddress((void**)&w2l, g_w2_l);

    // output layout handling: reference returns (out, attn_score)
    const int OUT_N = NB*NWAY*FEAT;
    const int SC_N  = NB*NWAY*NBASE;
    float* out_ptr   = (float*)d_out;
    float* score_ptr = score_sc;
    if (out_size >= OUT_N + SC_N) {
        out_ptr = (float*)d_out;
        score_ptr = (float*)d_out + OUT_N;
    } else if (out_size == SC_N) {
        out_ptr = out_sc;
        score_ptr = (float*)d_out;
    }

    // dynamic smem: max(tile stage 40KB, epilogue 128*136*4 = 69632B)
    const int SMEMB = 128*LDC*4;
    static int smem_set = 0;
    if (!smem_set) {
        cudaFuncSetAttribute(wmma_gemm, cudaFuncAttributeMaxDynamicSharedMemorySize, SMEMB);
        smem_set = 1;
    }

    // 0) weight prep: transpose + bf16 hi/lo split
    split_w_kernel<<<(512*512+255)/256, 256>>>(w_ks, 512, 512, wksh, wksl, 512, 512);
    split_w_kernel<<<(512*512+255)/256, 256>>>(w_vs, 512, 512, wvsh, wvsl, 512, 512);
    split_w_kernel<<<(512*320+255)/256, 256>>>(w_ks_sem, 300, 512, wkssh, wkssl, 320, 512);
    split_w_kernel<<<(384*320+255)/256, 256>>>(map_w1, 300, 300, w1h, w1l, 320, 384);
    split_w_kernel<<<(384*320+255)/256, 256>>>(map_w2, 300, 300, w2h, w2l, 320, 384);

    // 1) map_sem on base semantics (tensor cores, bf16x3)
    wmma_gemm<<<dim3(3, 63, NB), 256, SMEMB>>>(base_seman, w1h, w1l,
        NBASE, SEM, 320, SEM, SEM, (long long)NBASE*SEM, (long long)NBASE*SEM,
        map_b1, nullptr, 0, h, 1, 0);
    wmma_gemm<<<dim3(3, 63, NB), 256, SMEMB>>>(h, w2h, w2l,
        NBASE, SEM, 320, SEM, SEM, (long long)NBASE*SEM, (long long)NBASE*SEM,
        map_b2, nullptr, 0, calib, 0, 0);

    // 2) map_sem on support semantics (tiny, fp32)
    gemm_kernel<<<dim3(5, 2, 1), 256>>>(support_seman, map_w1, map_b1, nullptr, 0, nullptr,
                                        suph, NB*NWAY, SEM, SEM, 0, 0, 0, 1, 0);
    gemm_kernel<<<dim3(5, 2, 1), 256>>>(suph, map_w2, map_b2, nullptr, 0, nullptr,
                                        supcalib, NB*NWAY, SEM, SEM, 0, 0, 0, 0, 0);

    // 3) means over base classes -> avg -> gates
    mean_part_kernel<<<dim3(32, NB), 512>>>(base_weights, meanv, FEAT);
    mean_part_kernel<<<dim3(32, NB), 512>>>(calib, means, SEM);
    avg_kernel<<<NB, 1024>>>(meanv, means, avg);
    gate_kernel<<<NB, 512>>>(avg, visfuse_w, visfuse_b, gv, FEAT);
    gate_kernel<<<NB, 512>>>(avg, semfuse_w, semfuse_b, gs, SEM);

    // 4) ktot = (bw .* gv)@w_ks + (calib .* gs)@w_ks_sem   (tensor cores)
    wmma_gemm<<<dim3(4, 63, NB), 256, SMEMB>>>(base_weights, wksh, wksl,
        NBASE, FEAT, 512, FEAT, FEAT, (long long)NBASE*FEAT, (long long)NBASE*FEAT,
        nullptr, gv, FEAT, ktot, 0, 0);
    wmma_gemm<<<dim3(4, 63, NB), 256, SMEMB>>>(calib, wkssh, wkssl,
        NBASE, SEM, 320, FEAT, FEAT, (long long)NBASE*SEM, (long long)NBASE*FEAT,
        nullptr, gs, SEM, ktot, 0, 1);

    // 5) v = bw @ w_vs (tensor cores)
    wmma_gemm<<<dim3(4, 63, NB), 256, SMEMB>>>(base_weights, wvsh, wvsl,
        NBASE, FEAT, 512, FEAT, FEAT, (long long)NBASE*FEAT, (long long)NBASE*FEAT,
        nullptr, nullptr, 0, v, 0, 0);

    // 6) q_tot = support_feat@w_qs + supcalib@w_qs_sem (tiny, fp32)
    gemm_kernel<<<dim3(8, 2, 1), 256>>>(support_feat, w_qs, nullptr, nullptr, 0, nullptr,
                                        qtot, NB*NWAY, FEAT, FEAT, 0, 0, 0, 0, 0);
    gemm_kernel<<<dim3(8, 2, 1), 256>>>(supcalib, w_qs_sem, nullptr, nullptr, 0, nullptr,
                                        qtot, NB*NWAY, SEM, FEAT, 0, 0, 0, 0, 1);

    // 7) scores, softmax, attn@v, final proj + residual
    attn_kernel<<<dim3(NBASE/32, NB), 256>>>(ktot, qtot, score_ptr);
    softmax_kernel<<<NB*NWAY, 256>>>(score_ptr, attn);
    av_partial_kernel<<<dim3(NB, 25), 256>>>(attn, v, part);
    av_reduce_kernel<<<256, 256>>>(part, outpre);
    gemm_kernel<<<dim3(8, 2, 1), 256>>>(outpre, fc_w, nullptr, nullptr, 0, support_feat,
                                        out_ptr, NB*NWAY, FEAT, FEAT, 0, 0, 0, 0, 0);
}

// round 10
// speedup vs baseline: 1.9716x; 1.2657x over previous
#include <cuda_runtime.h>
#include <cuda_bf16.h>
#include <mma.h>
#include <math.h>
#include <stdint.h>

using namespace nvcuda;

// ---------------- problem constants ----------------
#define NB   8
#define NWAY 16
#define NBASE 8000
#define FEAT 512
#define SEM  300
#define SEMP 320                  // padded SEM (mult of 64)
#define MTOT (NB*NBASE)           // 64000
#define INV_TEMP (1.0f/22.62741699796952f)

// ---------------- device scratch (no allocs allowed) ----------------
__device__ float g_calib[NB*NBASE*SEM];    // calibrated base_seman (fp32, for means + split)
__device__ float g_ktot[NB*NBASE*FEAT];    // fused keys
__device__ float g_v[NB*NBASE*FEAT];       // values
__device__ float g_suph[NB*NWAY*SEM];
__device__ float g_supcalib[NB*NWAY*SEM];
__device__ float g_qtot[NB*NWAY*FEAT];
__device__ float g_meanv[NB*32*FEAT];
__device__ float g_means[NB*32*SEM];
__device__ float g_avg[NB*(FEAT+SEM)];
__device__ float g_gv[NB*FEAT];
__device__ float g_gs[NB*SEM];
__device__ float g_attn[NB*NWAY*NBASE];
__device__ float g_part[NB*25*NWAY*FEAT];
__device__ float g_outpre[NB*NWAY*FEAT];
__device__ float g_score_scratch[NB*NWAY*NBASE];
__device__ float g_out_scratch[NB*NWAY*FEAT];

// pre-split weights (transposed, [n, Kp]), bf16 hi/lo
__device__ __align__(256) __nv_bfloat16 g_wks_h[512*512],  g_wks_l[512*512];
__device__ __align__(256) __nv_bfloat16 g_wvs_h[512*512],  g_wvs_l[512*512];
__device__ __align__(256) __nv_bfloat16 g_wkss_h[512*SEMP], g_wkss_l[512*SEMP];
__device__ __align__(256) __nv_bfloat16 g_w1_h[384*SEMP],   g_w1_l[384*SEMP];
__device__ __align__(256) __nv_bfloat16 g_w2_h[384*SEMP],   g_w2_l[384*SEMP];

// pre-split activations, bf16 hi/lo, [b, m, Kp]
__device__ __align__(256) __nv_bfloat16 g_bsm_h[NB*NBASE*SEMP], g_bsm_l[NB*NBASE*SEMP];   // base_seman
__device__ __align__(256) __nv_bfloat16 g_h_h[NB*NBASE*SEMP],   g_h_l[NB*NBASE*SEMP];     // map_sem layer1 out
__device__ __align__(256) __nv_bfloat16 g_bw_h[NB*NBASE*FEAT],  g_bw_l[NB*NBASE*FEAT];    // base_weights (ungated)
__device__ __align__(256) __nv_bfloat16 g_bwg_h[NB*NBASE*FEAT], g_bwg_l[NB*NBASE*FEAT];   // base_weights * gate_vis
__device__ __align__(256) __nv_bfloat16 g_calg_h[NB*NBASE*SEMP], g_calg_l[NB*NBASE*SEMP]; // calib * gate_sem

__device__ __forceinline__ uint32_t smem_cast(const void* p) {
    uint32_t a;
    asm("{ .reg .u64 t; cvta.to.shared.u64 t, %1; cvt.u32.u64 %0, t; }" : "=r"(a) : "l"(p));
    return a;
}
#define CP16(dst, src) asm volatile("cp.async.cg.shared.global [%0], [%1], 16;" :: "r"(dst), "l"(src))
#define CPCOMMIT()     asm volatile("cp.async.commit_group;")
#define CPWAIT(n)      asm volatile("cp.async.wait_group %0;" :: "n"(n))

// ================= weight prep: transpose + bf16 hi/lo split =================
__global__ void split_w_kernel(const float* __restrict__ W, int K, int N,
                               __nv_bfloat16* __restrict__ Th, __nv_bfloat16* __restrict__ Tl,
                               int Kp, int Nr)
{
    long long i = (long long)blockIdx.x*256 + threadIdx.x;
    if (i >= (long long)Nr*Kp) return;
    int n = (int)(i / Kp), k = (int)(i % Kp);
    float v = (k < K && n < N) ? W[(long long)k*N + n] : 0.f;
    __nv_bfloat16 h = __float2bfloat16(v);
    Th[i] = h;
    Tl[i] = __float2bfloat16(v - __bfloat162float(h));
}

// ================= activation split: fp32 [b,M,K] (+gate) -> bf16 hi/lo [b,M,Kp] =====
__global__ void split_a_kernel(const float* __restrict__ X, int M, int K, int Kp,
                               long long sXb,
                               const float* __restrict__ gate, int gateLen,
                               __nv_bfloat16* __restrict__ H, __nv_bfloat16* __restrict__ L)
{
    int b = blockIdx.y;
    const float* Xb = X + (long long)b*sXb;
    const float* gt = gate ? gate + (long long)b*gateLen : nullptr;
    long long i = (long long)blockIdx.x*256 + threadIdx.x;
    if (i >= (long long)M*Kp) return;
    int m = (int)(i / Kp), k = (int)(i % Kp);
    float v = 0.f;
    if (k < K) {
        v = Xb[(long long)m*K + k];
        if (gt) v *= gt[k];
    }
    __nv_bfloat16 h = __float2bfloat16(v);
    long long o = (long long)b*M*Kp + i;
    H[o] = h;
    L[o] = __float2bfloat16(v - __bfloat162float(h));
}

// ================= WMMA bf16x3 GEMM, cp.async double-buffered =================
// C[b][m,n] = act( A[b] @ B^T + bias ); optional fp32 out (accum) and/or bf16 hi/lo out.
// A pre-split bf16 [M, Kp]; B pre-split bf16 [n, Kp]; block tile 128x128, K-chunk 32.
#define LDT 40     // smem tile leading dim in bf16 (32 + 8 pad, 80B rows)
#define LDC 136    // smem epilogue leading dim in f32
__global__ void __launch_bounds__(256) wmma_gemm2(
    const __nv_bfloat16* __restrict__ Ah, const __nv_bfloat16* __restrict__ Al,
    const __nv_bfloat16* __restrict__ Bh, const __nv_bfloat16* __restrict__ Bl,
    int Mrows, int Kp, int N, int Nc,
    long long sAb, long long sCb,
    const float* __restrict__ bias,
    float* __restrict__ C, int act, int accum,
    __nv_bfloat16* __restrict__ Ch, __nv_bfloat16* __restrict__ Cl,
    long long sCHb, int NcH)
{
    extern __shared__ char smem[];
    const int STAGE = 4*128*LDT;              // bf16 elems per stage
    __nv_bfloat16* s0 = (__nv_bfloat16*)smem;
    float* sC = (float*)smem;

    int b = blockIdx.z;
    const __nv_bfloat16* Abh = Ah + (long long)b*sAb;
    const __nv_bfloat16* Abl = Al + (long long)b*sAb;
    float* Cb = C ? C + (long long)b*sCb : nullptr;
    int m0 = blockIdx.y*128, n0 = blockIdx.x*128;
    int tid = threadIdx.x, wid = tid >> 5;
    int wm = (wid & 3)*32, wn = (wid >> 2)*64;

    // per-thread load assignments: 512 16B-segments per matrix, 2 per thread
    int lrow0 = tid >> 2,         lq0 = tid & 3;
    int lrow1 = (tid+256) >> 2,   lq1 = (tid+256) & 3;
    // clamp A rows (garbage rows never stored; B rows always in-bounds by padding)
    int am0 = m0 + lrow0; if (am0 >= Mrows) am0 = Mrows-1;
    int am1 = m0 + lrow1; if (am1 >= Mrows) am1 = Mrows-1;

    auto load_chunk = [&](int c, int buf) {
        int k0 = c*32;
        __nv_bfloat16* st = s0 + buf*STAGE;
        __nv_bfloat16* dAh = st;
        __nv_bfloat16* dAl = st + 128*LDT;
        __nv_bfloat16* dBh = st + 2*128*LDT;
        __nv_bfloat16* dBl = st + 3*128*LDT;
        const __nv_bfloat16* a0h = Abh + (long long)am0*Kp + k0;
        const __nv_bfloat16* a1h = Abh + (long long)am1*Kp + k0;
        const __nv_bfloat16* a0l = Abl + (long long)am0*Kp + k0;
        const __nv_bfloat16* a1l = Abl + (long long)am1*Kp + k0;
        CP16(smem_cast(&dAh[lrow0*LDT + lq0*8]), a0h + lq0*8);
        CP16(smem_cast(&dAh[lrow1*LDT + lq1*8]), a1h + lq1*8);
        CP16(smem_cast(&dAl[lrow0*LDT + lq0*8]), a0l + lq0*8);
        CP16(smem_cast(&dAl[lrow1*LDT + lq1*8]), a1l + lq1*8);
        const __nv_bfloat16* b0h = Bh + (long long)(n0+lrow0)*Kp + k0;
        const __nv_bfloat16* b1h = Bh + (long long)(n0+lrow1)*Kp + k0;
        const __nv_bfloat16* b0l = Bl + (long long)(n0+lrow0)*Kp + k0;
        const __nv_bfloat16* b1l = Bl + (long long)(n0+lrow1)*Kp + k0;
        CP16(smem_cast(&dBh[lrow0*LDT + lq0*8]), b0h + lq0*8);
        CP16(smem_cast(&dBh[lrow1*LDT + lq1*8]), b1h + lq1*8);
        CP16(smem_cast(&dBl[lrow0*LDT + lq0*8]), b0l + lq0*8);
        CP16(smem_cast(&dBl[lrow1*LDT + lq1*8]), b1l + lq1*8);
    };

    wmma::fragment<wmma::accumulator, 16, 16, 16, float> acc[2][4];
    #pragma unroll
    for (int i = 0; i < 2; i++)
        #pragma unroll
        for (int j = 0; j < 4; j++) wmma::fill_fragment(acc[i][j], 0.f);

    const int nc = Kp/32;
    load_chunk(0, 0);
    CPCOMMIT();
    for (int c = 0; c < nc; c++) {
        int buf = c & 1;
        if (c+1 < nc) { load_chunk(c+1, (c+1) & 1); CPCOMMIT(); CPWAIT(1); }
        else          { CPWAIT(0); }
        __syncthreads();
        __nv_bfloat16* st = s0 + buf*STAGE;
        __nv_bfloat16* sAh = st;
        __nv_bfloat16* sAl = st + 128*LDT;
        __nv_bfloat16* sBh = st + 2*128*LDT;
        __nv_bfloat16* sBl = st + 3*128*LDT;
        #pragma unroll
        for (int ks = 0; ks < 2; ks++) {
            wmma::fragment<wmma::matrix_a, 16, 16, 16, __nv_bfloat16, wmma::row_major> ah[2], al[2];
            wmma::fragment<wmma::matrix_b, 16, 16, 16, __nv_bfloat16, wmma::col_major> bh[4], bl[4];
            #pragma unroll
            for (int i = 0; i < 2; i++) {
                wmma::load_matrix_sync(ah[i], &sAh[(wm + i*16)*LDT + ks*16], LDT);
                wmma::load_matrix_sync(al[i], &sAl[(wm + i*16)*LDT + ks*16], LDT);
            }
            #pragma unroll
            for (int j = 0; j < 4; j++) {
                wmma::load_matrix_sync(bh[j], &sBh[(wn + j*16)*LDT + ks*16], LDT);
                wmma::load_matrix_sync(bl[j], &sBl[(wn + j*16)*LDT + ks*16], LDT);
            }
            #pragma unroll
            for (int i = 0; i < 2; i++)
                #pragma unroll
                for (int j = 0; j < 4; j++) {
                    wmma::mma_sync(acc[i][j], ah[i], bh[j], acc[i][j]);
                    wmma::mma_sync(acc[i][j], ah[i], bl[j], acc[i][j]);
                    wmma::mma_sync(acc[i][j], al[i], bh[j], acc[i][j]);
                }
        }
        __syncthreads();
    }

    // ---- epilogue: frags -> smem -> outputs ----
    #pragma unroll
    for (int i = 0; i < 2; i++)
        #pragma unroll
        for (int j = 0; j < 4; j++)
            wmma::store_matrix_sync(&sC[(wm + i*16)*LDC + wn + j*16], acc[i][j], LDC,
                                    wmma::mem_row_major);
    __syncthreads();
    for (int j = 0; j < 64; j++) {
        int lin = tid + j*256;                // 16384 = 128x128
        int row = lin >> 7, col = lin & 127;
        int gm = m0 + row, gn = n0 + col;
        if (gm >= Mrows) continue;
        float v = 0.f;
        if (gn < N) {
            v = sC[row*LDC + col];
            if (bias) v += bias[gn];
            if (act)  v = (v >= 0.f) ? v : 0.1f*v;
            if (Cb) {
                long long idx = (long long)gm*Nc + gn;
                if (accum) v += Cb[idx];
                Cb[idx] = v;
            }
        }
        if (Ch && gn < NcH) {
            long long o = sCHb*b + (long long)gm*NcH + gn;
            __nv_bfloat16 hh = __float2bfloat16(v);
            Ch[o] = hh;
            Cl[o] = __float2bfloat16(v - __bfloat162float(hh));
        }
    }
}

// ---------------- fp32 tiled GEMM (small matrices only) ----------------
#define BM 64
#define BN 64
#define BK 16
__global__ void gemm_kernel(const float* __restrict__ A, const float* __restrict__ B,
                            const float* __restrict__ bias,
                            const float* __restrict__ gate, int gateK,
                            const float* __restrict__ resid,
                            float* __restrict__ C,
                            int M, int K, int N,
                            long long sAb, long long sBb, long long sCb,
                            int act, int accum)
{
    int b = blockIdx.z;
    A += (long long)b * sAb;
    B += (long long)b * sBb;
    C += (long long)b * sCb;
    const float* gt = gate ? (gate + (long long)b * gateK) : nullptr;

    __shared__ float As[BK][BM+1];
    __shared__ float Bs[BK][BN+1];

    int tid = threadIdx.x;
    int tx = tid & 15, ty = tid >> 4;
    int m0 = blockIdx.y * BM, n0 = blockIdx.x * BN;

    float acc[4][4];
    #pragma unroll
    for (int i = 0; i < 4; i++)
        #pragma unroll
        for (int j = 0; j < 4; j++) acc[i][j] = 0.f;

    for (int k0 = 0; k0 < K; k0 += BK) {
        #pragma unroll
        for (int l = 0; l < 4; l++) {
            int i = tid + l*256;
            int ar = i >> 4, ac = i & 15;
            int gm = m0 + ar, gk = k0 + ac;
            float vv = 0.f;
            if (gm < M && gk < K) {
                vv = A[(long long)gm*K + gk];
                if (gt) vv *= gt[gk];
            }
            As[ac][ar] = vv;
        }
        #pragma unroll
        for (int l = 0; l < 4; l++) {
            int i = tid + l*256;
            int br = i >> 6, bc = i & 63;
            int gk = k0 + br, gn = n0 + bc;
            Bs[br][bc] = (gk < K && gn < N) ? B[(long long)gk*N + gn] : 0.f;
        }
        __syncthreads();
        #pragma unroll
        for (int kk = 0; kk < BK; kk++) {
            float a[4], bb[4];
            #pragma unroll
            for (int i = 0; i < 4; i++) a[i] = As[kk][ty*4+i];
            #pragma unroll
            for (int j = 0; j < 4; j++) bb[j] = Bs[kk][tx*4+j];
            #pragma unroll
            for (int i = 0; i < 4; i++)
                #pragma unroll
                for (int j = 0; j < 4; j++)
                    acc[i][j] += a[i]*bb[j];
        }
        __syncthreads();
    }

    #pragma unroll
    for (int i = 0; i < 4; i++) {
        int gm = m0 + ty*4 + i;
        if (gm >= M) continue;
        #pragma unroll
        for (int j = 0; j < 4; j++) {
            int gn = n0 + tx*4 + j;
            if (gn >= N) continue;
            float vv = acc[i][j];
            if (bias) vv += bias[gn];
            if (act == 1) vv = (vv >= 0.f) ? vv : 0.1f*vv;
            if (resid) vv += resid[(long long)gm*N + gn];
            long long idx = (long long)gm*N + gn;
            if (accum) vv += C[idx];
            C[idx] = vv;
        }
    }
}

// ---------------- column means (partial over 250-row chunks) ----------------
__global__ void mean_part_kernel(const float* __restrict__ X, float* __restrict__ part, int C)
{
    int b = blockIdx.y, ch = blockIdx.x;
    int c = threadIdx.x;
    if (c >= C) return;
    const float* p = X + ((long long)b*NBASE + ch*250)*C + c;
    float s = 0.f;
    for (int r = 0; r < 250; r++) s += p[(long long)r*C];
    part[((long long)b*32 + ch)*C + c] = s;
}

__global__ void avg_kernel(const float* __restrict__ pv, const float* __restrict__ ps,
                           float* __restrict__ avg)
{
    int b = blockIdx.x, c = threadIdx.x;
    if (c < FEAT) {
        float s = 0.f;
        for (int ch = 0; ch < 32; ch++) s += pv[((long long)b*32+ch)*FEAT + c];
        avg[b*(FEAT+SEM) + c] = s * (1.0f/NBASE);
    } else if (c < FEAT + SEM) {
        int cc = c - FEAT;
        float s = 0.f;
        for (int ch = 0; ch < 32; ch++) s += ps[((long long)b*32+ch)*SEM + cc];
        avg[b*(FEAT+SEM) + FEAT + cc] = s * (1.0f/NBASE);
    }
}

__global__ void gate_kernel(const float* __restrict__ avg, const float* __restrict__ W,
                            const float* __restrict__ bias, float* __restrict__ gate, int N)
{
    int b = blockIdx.x, j = threadIdx.x;
    __shared__ float av[FEAT+SEM];
    for (int i = threadIdx.x; i < FEAT+SEM; i += blockDim.x) av[i] = avg[b*(FEAT+SEM) + i];
    __syncthreads();
    if (j < N) {
        float s = bias[j];
        for (int k = 0; k < FEAT+SEM; k++) s += av[k]*W[(long long)k*N + j];
        gate[b*N + j] = 1.f + 1.f/(1.f + expf(-s));
    }
}

// ---------------- attention scores ----------------
__global__ void attn_kernel(const float* __restrict__ ktot, const float* __restrict__ qtot,
                            float* __restrict__ score)
{
    int b = blockIdx.y;
    int n0 = blockIdx.x * 32;
    __shared__ float qs[NWAY][FEAT];
    __shared__ float ks[32][33];
    const float* q = qtot + (long long)b*NWAY*FEAT;
    for (int i = threadIdx.x; i < NWAY*FEAT; i += 256) qs[i>>9][i&511] = q[i];
    int r  = threadIdx.x & 31;
    int wg = threadIdx.x >> 5;
    float acc0 = 0.f, acc1 = 0.f;
    const float* kb = ktot + ((long long)b*NBASE + n0)*FEAT;
    for (int k0 = 0; k0 < FEAT; k0 += 32) {
        __syncthreads();
        for (int i = threadIdx.x; i < 32*32; i += 256) {
            int rr = i >> 5, cc = i & 31;
            ks[rr][cc] = kb[(long long)rr*FEAT + k0 + cc];
        }
        __syncthreads();
        #pragma unroll
        for (int kk = 0; kk < 32; kk++) {
            float kv = ks[r][kk];
            acc0 += kv * qs[2*wg  ][k0+kk];
            acc1 += kv * qs[2*wg+1][k0+kk];
        }
    }
    score[((long long)b*NWAY + 2*wg  )*NBASE + n0 + r] = acc0 * INV_TEMP;
    score[((long long)b*NWAY + 2*wg+1)*NBASE + n0 + r] = acc1 * INV_TEMP;
}

// ---------------- softmax ----------------
__global__ void softmax_kernel(const float* __restrict__ score, float* __restrict__ attn)
{
    int row = blockIdx.x;
    const float* s = score + (long long)row*NBASE;
    float* a = attn + (long long)row*NBASE;
    __shared__ float red[256];
    float mx = -1e30f;
    for (int i = threadIdx.x; i < NBASE; i += 256) mx = fmaxf(mx, s[i]);
    red[threadIdx.x] = mx; __syncthreads();
    for (int st = 128; st > 0; st >>= 1) {
        if (threadIdx.x < st) red[threadIdx.x] = fmaxf(red[threadIdx.x], red[threadIdx.x+st]);
        __syncthreads();
    }
    mx = red[0]; __syncthreads();
    float sum = 0.f;
    for (int i = threadIdx.x; i < NBASE; i += 256) {
        float e = expf(s[i] - mx);
        a[i] = e;
        sum += e;
    }
    red[threadIdx.x] = sum; __syncthreads();
    for (int st = 128; st > 0; st >>= 1) {
        if (threadIdx.x < st) red[threadIdx.x] += red[threadIdx.x+st];
        __syncthreads();
    }
    float inv = 1.f/red[0];
    for (int i = threadIdx.x; i < NBASE; i += 256) a[i] *= inv;
}

// ---------------- attn @ v, deterministic split-K ----------------
__global__ void av_partial_kernel(const float* __restrict__ attn, const float* __restrict__ v,
                                  float* __restrict__ part)
{
    int b  = blockIdx.x;
    int ch = blockIdx.y;
    int n0 = ch * 320;
    __shared__ float as[NWAY][32];
    int c0 = threadIdx.x;
    float acc[NWAY][2];
    #pragma unroll
    for (int w = 0; w < NWAY; w++) { acc[w][0] = 0.f; acc[w][1] = 0.f; }

    for (int nb = 0; nb < 320; nb += 32) {
        __syncthreads();
        for (int i = threadIdx.x; i < NWAY*32; i += 256) {
            int w = i >> 5, nn = i & 31;
            as[w][nn] = attn[((long long)b*NWAY + w)*NBASE + n0 + nb + nn];
        }
        __syncthreads();
        for (int nn = 0; nn < 32; nn++) {
            const float* vr = v + ((long long)b*NBASE + n0 + nb + nn)*FEAT;
            float v0 = vr[c0], v1 = vr[c0+256];
            #pragma unroll
            for (int w = 0; w < NWAY; w++) {
                acc[w][0] += as[w][nn]*v0;
                acc[w][1] += as[w][nn]*v1;
            }
        }
    }
    #pragma unroll
    for (int w = 0; w < NWAY; w++) {
        part[(((long long)b*25 + ch)*NWAY + w)*FEAT + c0      ] = acc[w][0];
        part[(((long long)b*25 + ch)*NWAY + w)*FEAT + c0 + 256] = acc[w][1];
    }
}

__global__ void av_reduce_kernel(const float* __restrict__ part, float* __restrict__ outpre)
{
    long long i = (long long)blockIdx.x*256 + threadIdx.x;
    int c = i & 511;
    long long bw = i >> 9;
    int w = bw & 15;
    int b = (int)(bw >> 4);
    float s = 0.f;
    for (int ch = 0; ch < 25; ch++)
        s += part[(((long long)b*25 + ch)*NWAY + w)*FEAT + c];
    outpre[i] = s;
}

// ---------------- host ----------------
extern "C" void kernel_launch(void* const* d_in, const int* in_sizes, int n_in,
                              void* d_out, int out_size)
{
    const float* support_feat  = (const float*)d_in[0];
    const float* base_weights  = (const float*)d_in[1];
    const float* support_seman = (const float*)d_in[2];
    const float* base_seman    = (const float*)d_in[3];
    const float* map_w1 = (const float*)d_in[4];
    const float* map_b1 = (const float*)d_in[5];
    const float* map_w2 = (const float*)d_in[6];
    const float* map_b2 = (const float*)d_in[7];
    const float* visfuse_w = (const float*)d_in[8];
    const float* visfuse_b = (const float*)d_in[9];
    const float* semfuse_w = (const float*)d_in[10];
    const float* semfuse_b = (const float*)d_in[11];
    const float* w_qs = (const float*)d_in[12];
    const float* w_ks = (const float*)d_in[13];
    const float* w_vs = (const float*)d_in[14];
    const float* w_qs_sem = (const float*)d_in[15];
    const float* w_ks_sem = (const float*)d_in[16];
    const float* fc_w = (const float*)d_in[17];

    float *calib, *ktot, *v, *suph, *supcalib, *qtot;
    float *meanv, *means, *avg, *gv, *gs, *attn, *part, *outpre, *score_sc, *out_sc;
    cudaGetSymbolAddress((void**)&calib, g_calib);
    cudaGetSymbolAddress((void**)&ktot, g_ktot);
    cudaGetSymbolAddress((void**)&v, g_v);
    cudaGetSymbolAddress((void**)&suph, g_suph);
    cudaGetSymbolAddress((void**)&supcalib, g_supcalib);
    cudaGetSymbolAddress((void**)&qtot, g_qtot);
    cudaGetSymbolAddress((void**)&meanv, g_meanv);
    cudaGetSymbolAddress((void**)&means, g_means);
    cudaGetSymbolAddress((void**)&avg, g_avg);
    cudaGetSymbolAddress((void**)&gv, g_gv);
    cudaGetSymbolAddress((void**)&gs, g_gs);
    cudaGetSymbolAddress((void**)&attn, g_attn);
    cudaGetSymbolAddress((void**)&part, g_part);
    cudaGetSymbolAddress((void**)&outpre, g_outpre);
    cudaGetSymbolAddress((void**)&score_sc, g_score_scratch);
    cudaGetSymbolAddress((void**)&out_sc, g_out_scratch);

    __nv_bfloat16 *wksh, *wksl, *wvsh, *wvsl, *wkssh, *wkssl, *w1h, *w1l, *w2h, *w2l;
    cudaGetSymbolAddress((void**)&wksh, g_wks_h);   cudaGetSymbolAddress((void**)&wksl, g_wks_l);
    cudaGetSymbolAddress((void**)&wvsh, g_wvs_h);   cudaGetSymbolAddress((void**)&wvsl, g_wvs_l);
    cudaGetSymbolAddress((void**)&wkssh, g_wkss_h); cudaGetSymbolAddress((void**)&wkssl, g_wkss_l);
    cudaGetSymbolAddress((void**)&w1h, g_w1_h);     cudaGetSymbolAddress((void**)&w1l, g_w1_l);
    cudaGetSymbolAddress((void**)&w2h, g_w2_h);     cudaGetSymbolAddress((void**)&w2l, g_w2_l);

    __nv_bfloat16 *bsmh, *bsml, *hh, *hl, *bwh, *bwl, *bwgh, *bwgl, *calgh, *calgl;
    cudaGetSymbolAddress((void**)&bsmh, g_bsm_h);   cudaGetSymbolAddress((void**)&bsml, g_bsm_l);
    cudaGetSymbolAddress((void**)&hh, g_h_h);       cudaGetSymbolAddress((void**)&hl, g_h_l);
    cudaGetSymbolAddress((void**)&bwh, g_bw_h);     cudaGetSymbolAddress((void**)&bwl, g_bw_l);
    cudaGetSymbolAddress((void**)&bwgh, g_bwg_h);   cudaGetSymbolAddress((void**)&bwgl, g_bwg_l);
    cudaGetSymbolAddress((void**)&calgh, g_calg_h); cudaGetSymbolAddress((void**)&calgl, g_calg_l);

    // output layout handling: reference returns (out, attn_score)
    const int OUT_N = NB*NWAY*FEAT;
    const int SC_N  = NB*NWAY*NBASE;
    float* out_ptr   = (float*)d_out;
    float* score_ptr = score_sc;
    if (out_size >= OUT_N + SC_N) {
        out_ptr = (float*)d_out;
        score_ptr = (float*)d_out + OUT_N;
    } else if (out_size == SC_N) {
        out_ptr = out_sc;
        score_ptr = (float*)d_out;
    }

    // dynamic smem: 2 stages x 40KB (epilogue 69,632B reuses it)
    const int SMEMB = 2 * 4*128*LDT*2;   // 81,920
    cudaFuncSetAttribute(wmma_gemm2, cudaFuncAttributeMaxDynamicSharedMemorySize, SMEMB);

    const long long sBSM = (long long)NBASE*SEMP;
    const long long sBW  = (long long)NBASE*FEAT;

    // 0) weight prep
    split_w_kernel<<<(512*512+255)/256, 256>>>(w_ks, 512, 512, wksh, wksl, 512, 512);
    split_w_kernel<<<(512*512+255)/256, 256>>>(w_vs, 512, 512, wvsh, wvsl, 512, 512);
    split_w_kernel<<<(512*SEMP+255)/256, 256>>>(w_ks_sem, SEM, 512, wkssh, wkssl, SEMP, 512);
    split_w_kernel<<<(384*SEMP+255)/256, 256>>>(map_w1, SEM, SEM, w1h, w1l, SEMP, 384);
    split_w_kernel<<<(384*SEMP+255)/256, 256>>>(map_w2, SEM, SEM, w2h, w2l, SEMP, 384);

    // 0b) activation pre-splits that need no gates
    split_a_kernel<<<dim3((NBASE*SEMP+255)/256, NB), 256>>>(base_seman, NBASE, SEM, SEMP,
        (long long)NBASE*SEM, nullptr, 0, bsmh, bsml);
    split_a_kernel<<<dim3((NBASE*FEAT+255)/256, NB), 256>>>(base_weights, NBASE, FEAT, FEAT,
        (long long)NBASE*FEAT, nullptr, 0, bwh, bwl);

    // 1) map_sem on base semantics: h (bf16 hi/lo out only), then calib (fp32)
    wmma_gemm2<<<dim3(3, 63, NB), 256, SMEMB>>>(bsmh, bsml, w1h, w1l,
        NBASE, SEMP, SEM, 0, sBSM, 0, map_b1, nullptr, 1, 0,
        hh, hl, sBSM, SEMP);
    wmma_gemm2<<<dim3(3, 63, NB), 256, SMEMB>>>(hh, hl, w2h, w2l,
        NBASE, SEMP, SEM, SEM, sBSM, (long long)NBASE*SEM, map_b2, calib, 0, 0,
        nullptr, nullptr, 0, 0);

    // 2) map_sem on support semantics (tiny, fp32)
    gemm_kernel<<<dim3(5, 2, 1), 256>>>(support_seman, map_w1, map_b1, nullptr, 0, nullptr,
                                        suph, NB*NWAY, SEM, SEM, 0, 0, 0, 1, 0);
    gemm_kernel<<<dim3(5, 2, 1), 256>>>(suph, map_w2, map_b2, nullptr, 0, nullptr,
                                        supcalib, NB*NWAY, SEM, SEM, 0, 0, 0, 0, 0);

    // 3) means over base classes -> avg -> gates
    mean_part_kernel<<<dim3(32, NB), 512>>>(base_weights, meanv, FEAT);
    mean_part_kernel<<<dim3(32, NB), 512>>>(calib, means, SEM);
    avg_kernel<<<NB, 1024>>>(meanv, means, avg);
    gate_kernel<<<NB, 512>>>(avg, visfuse_w, visfuse_b, gv, FEAT);
    gate_kernel<<<NB, 512>>>(avg, semfuse_w, semfuse_b, gs, SEM);

    // 3b) gated activation splits
    split_a_kernel<<<dim3((NBASE*FEAT+255)/256, NB), 256>>>(base_weights, NBASE, FEAT, FEAT,
        (long long)NBASE*FEAT, gv, FEAT, bwgh, bwgl);
    split_a_kernel<<<dim3((NBASE*SEMP+255)/256, NB), 256>>>(calib, NBASE, SEM, SEMP,
        (long long)NBASE*SEM, gs, SEM, calgh, calgl);

    // 4) ktot = (bw.*gv)@w_ks + (calib.*gs)@w_ks_sem
    wmma_gemm2<<<dim3(4, 63, NB), 256, SMEMB>>>(bwgh, bwgl, wksh, wksl,
        NBASE, FEAT, FEAT, FEAT, sBW, sBW, nullptr, ktot, 0, 0,
        nullptr, nullptr, 0, 0);
    wmma_gemm2<<<dim3(4, 63, NB), 256, SMEMB>>>(calgh, calgl, wkssh, wkssl,
        NBASE, SEMP, FEAT, FEAT, sBSM, sBW, nullptr, ktot, 0, 1,
        nullptr, nullptr, 0, 0);

    // 5) v = bw @ w_vs
    wmma_gemm2<<<dim3(4, 63, NB), 256, SMEMB>>>(bwh, bwl, wvsh, wvsl,
        NBASE, FEAT, FEAT, FEAT, sBW, sBW, nullptr, v, 0, 0,
        nullptr, nullptr, 0, 0);

    // 6) q_tot = support_feat@w_qs + supcalib@w_qs_sem (tiny, fp32)
    gemm_kernel<<<dim3(8, 2, 1), 256>>>(support_feat, w_qs, nullptr, nullptr, 0, nullptr,
                                        qtot, NB*NWAY, FEAT, FEAT, 0, 0, 0, 0, 0);
    gemm_kernel<<<dim3(8, 2, 1), 256>>>(supcalib, w_qs_sem, nullptr, nullptr, 0, nullptr,
                                        qtot, NB*NWAY, SEM, FEAT, 0, 0, 0, 0, 1);

    // 7) scores, softmax, attn@v, final proj + residual
    attn_kernel<<<dim3(NBASE/32, NB), 256>>>(ktot, qtot, score_ptr);
    softmax_kernel<<<NB*NWAY, 256>>>(score_ptr, attn);
    av_partial_kernel<<<dim3(NB, 25), 256>>>(attn, v, part);
    av_reduce_kernel<<<256, 256>>>(part, outpre);
    gemm_kernel<<<dim3(8, 2, 1), 256>>>(outpre, fc_w, nullptr, nullptr, 0, support_feat,
                                        out_ptr, NB*NWAY, FEAT, FEAT, 0, 0, 0, 0, 0);
}

// round 14
// speedup vs baseline: 2.7528x; 1.3962x over previous
#include <cuda_runtime.h>
#include <cuda_fp16.h>
#include <mma.h>
#include <math.h>
#include <stdint.h>

using namespace nvcuda;

// ---------------- problem constants ----------------
#define NB   8
#define NWAY 16
#define NBASE 8000
#define FEAT 512
#define SEM  300
#define SEMP 320                  // padded SEM (mult of 64)
#define INV_TEMP (1.0f/22.62741699796952f)

// ---------------- device scratch (no allocs allowed) ----------------
__device__ float g_calib[NB*NBASE*SEM];    // calibrated base_seman (fp32, for means)
__device__ float g_ktot[NB*NBASE*FEAT];    // fused keys
__device__ float g_v[NB*NBASE*FEAT];       // values
__device__ float g_suph[NB*NWAY*SEM];
__device__ float g_supcalib[NB*NWAY*SEM];
__device__ float g_qtot[NB*NWAY*FEAT];
__device__ float g_meanv[NB*32*FEAT];
__device__ float g_means[NB*32*SEM];
__device__ float g_avg[NB*(FEAT+SEM)];
__device__ float g_gv[NB*FEAT];
__device__ float g_gs[NB*SEM];
__device__ float g_attn[NB*NWAY*NBASE];
__device__ float g_part[NB*25*NWAY*FEAT];
__device__ float g_outpre[NB*NWAY*FEAT];
__device__ float g_score_scratch[NB*NWAY*NBASE];
__device__ float g_out_scratch[NB*NWAY*FEAT];

// shared (un-gated) weights, transposed [n, Kp], fp16 hi/lo
__device__ __align__(256) __half g_wvs_h[512*512], g_wvs_l[512*512];
__device__ __align__(256) __half g_w1_h[384*SEMP], g_w1_l[384*SEMP];
__device__ __align__(256) __half g_w2_h[384*SEMP], g_w2_l[384*SEMP];
// per-batch gate-scaled weights, [b][n][Kp], fp16 hi/lo
__device__ __align__(256) __half g_wksg_h[NB*512*512],  g_wksg_l[NB*512*512];
__device__ __align__(256) __half g_wkssg_h[NB*512*SEMP], g_wkssg_l[NB*512*SEMP];

// fp16 activations (hi only), [b, m, Kp]
__device__ __align__(256) __half g_bsm_h[NB*NBASE*SEMP];  // base_seman
__device__ __align__(256) __half g_h_h[NB*NBASE*SEMP];    // map_sem layer1 out
__device__ __align__(256) __half g_bw_h[NB*NBASE*FEAT];   // base_weights
__device__ __align__(256) __half g_cal_h[NB*NBASE*SEMP];  // calib

__device__ __forceinline__ uint32_t smem_cast(const void* p) {
    uint32_t a;
    asm("{ .reg .u64 t; cvta.to.shared.u64 t, %1; cvt.u32.u64 %0, t; }" : "=r"(a) : "l"(p));
    return a;
}
#define CP16(dst, src) asm volatile("cp.async.cg.shared.global [%0], [%1], 16;" :: "r"(dst), "l"(src))
#define CPCOMMIT()     asm volatile("cp.async.commit_group;")
#define CPWAIT(n)      asm volatile("cp.async.wait_group %0;" :: "n"(n))

// ========== weight prep: transpose + fp16 hi/lo split (shared weights) ==========
__global__ void split_w_kernel(const float* __restrict__ W, int K, int N,
                               __half* __restrict__ Th, __half* __restrict__ Tl,
                               int Kp, int Nr)
{
    long long i = (long long)blockIdx.x*256 + threadIdx.x;
    if (i >= (long long)Nr*Kp) return;
    int n = (int)(i / Kp), k = (int)(i % Kp);
    float v = (k < K && n < N) ? W[(long long)k*N + n] : 0.f;
    __half h = __float2half(v);
    Th[i] = h;
    Tl[i] = __float2half(v - __half2float(h));
}

// ========== gate-scaled weight prep: W'[b][n][k] = gate[b][k]*W[k][n], split ==========
__global__ void scale_split_w_kernel(const float* __restrict__ W, int K, int N,
                                     const float* __restrict__ gate,
                                     __half* __restrict__ Th, __half* __restrict__ Tl,
                                     int Kp, int Nr)
{
    int b = blockIdx.y;
    long long i = (long long)blockIdx.x*256 + threadIdx.x;
    if (i >= (long long)Nr*Kp) return;
    int n = (int)(i / Kp), k = (int)(i % Kp);
    float v = (k < K && n < N) ? W[(long long)k*N + n] * gate[(long long)b*K + k] : 0.f;
    __half h = __float2half(v);
    long long o = (long long)b*Nr*Kp + i;
    Th[o] = h;
    Tl[o] = __float2half(v - __half2float(h));
}

// ========== activation convert: fp32 [b,M,K] -> fp16 [b,M,Kp] ==========
__global__ void conv_a_kernel(const float* __restrict__ X, int M, int K, int Kp,
                              long long sXb, __half* __restrict__ H)
{
    int b = blockIdx.y;
    const float* Xb = X + (long long)b*sXb;
    long long i = (long long)blockIdx.x*256 + threadIdx.x;
    if (i >= (long long)M*Kp) return;
    int m = (int)(i / Kp), k = (int)(i % Kp);
    float v = (k < K) ? Xb[(long long)m*K + k] : 0.f;
    H[(long long)b*M*Kp + i] = __float2half(v);
}

// ================= WMMA fp16x2 GEMM, dual-K-source, cp.async double-buffered ========
// C[b] = act( A1[b] @ B1[b]^T + A2[b] @ B2[b]^T + bias )
// A fp16 [M, Kp] hi-only; B fp16 [n, Kp] hi+lo; acc = Ah*Bh + Ah*Bl.
// Block tile 128x128, 8 warps as 2(m)x4(n), warp tile 64x32, K-chunk 32.
#define LDT 40     // smem tile leading dim in halves (32 + 8 pad, 80B rows)
#define LDC 136    // smem epilogue leading dim in f32
__global__ void __launch_bounds__(256, 2) wmma_gemm3(
    const __half* __restrict__ A1, const __half* __restrict__ B1h, const __half* __restrict__ B1l,
    int K1p, long long sA1b, long long sB1b,
    const __half* __restrict__ A2, const __half* __restrict__ B2h, const __half* __restrict__ B2l,
    int K2p, long long sA2b, long long sB2b,
    int Mrows, int N, int Nc, long long sCb,
    const float* __restrict__ bias,
    float* __restrict__ C, int act,
    __half* __restrict__ Ch, long long sCHb, int NcH)
{
    extern __shared__ char smem[];
    const int STAGE = 3*128*LDT;              // halves per stage (Ah, Bh, Bl)
    __half* s0 = (__half*)smem;
    float* sC = (float*)smem;

    int b = blockIdx.z;
    int m0 = blockIdx.y*128, n0 = blockIdx.x*128;
    int tid = threadIdx.x, wid = tid >> 5;
    int wm = (wid & 1)*64, wn = (wid >> 1)*32;

    // load assignment: 512 16B-segs per matrix, 2 per thread
    int r0 = tid >> 1;            // rows 0..127 (2 segs each)
    int q0 = (tid & 1)*2;         // seg cols {0,1} or {2,3}
    int am0 = m0 + r0; if (am0 >= Mrows) am0 = Mrows - 1;

    auto load_chunk = [&](int c, int buf) {
        int k0 = c*32;
        const __half *Ap, *Bph, *Bpl;
        if (k0 < K1p) {
            Ap  = A1 + (long long)b*sA1b + k0;
            Bph = B1h + (long long)b*sB1b + k0;
            Bpl = B1l + (long long)b*sB1b + k0;
        } else {
            int k2 = k0 - K1p;
            Ap  = A2 + (long long)b*sA2b + k2;
            Bph = B2h + (long long)b*sB2b + k2;
            Bpl = B2l + (long long)b*sB2b + k2;
        }
        int Kp = (k0 < K1p) ? K1p : K2p;
        __half* st = s0 + buf*STAGE;
        __half* dA  = st;
        __half* dBh = st + 128*LDT;
        __half* dBl = st + 2*128*LDT;
        uint32_t offA  = smem_cast(&dA [r0*LDT + q0*8]);
        uint32_t offBh = smem_cast(&dBh[r0*LDT + q0*8]);
        uint32_t offBl = smem_cast(&dBl[r0*LDT + q0*8]);
        const __half* aS  = Ap  + (long long)am0*Kp + q0*8;
        const __half* bSh = Bph + (long long)(n0 + r0)*Kp + q0*8;
        const __half* bSl = Bpl + (long long)(n0 + r0)*Kp + q0*8;
        CP16(offA,       aS);
        CP16(offA  + 16, aS  + 8);
        CP16(offBh,      bSh);
        CP16(offBh + 16, bSh + 8);
        CP16(offBl,      bSl);
        CP16(offBl + 16, bSl + 8);
    };

    wmma::fragment<wmma::accumulator, 16, 16, 16, float> acc[4][2];
    #pragma unroll
    for (int i = 0; i < 4; i++)
        #pragma unroll
        for (int j = 0; j < 2; j++) wmma::fill_fragment(acc[i][j], 0.f);

    const int nc = (K1p + K2p)/32;
    load_chunk(0, 0);
    CPCOMMIT();
    for (int c = 0; c < nc; c++) {
        int buf = c & 1;
        CPWAIT(0);
        __syncthreads();
        if (c+1 < nc) { load_chunk(c+1, buf ^ 1); CPCOMMIT(); }
        __half* st = s0 + buf*STAGE;
        __half* sA  = st;
        __half* sBh = st + 128*LDT;
        __half* sBl = st + 2*128*LDT;
        #pragma unroll
        for (int ks = 0; ks < 2; ks++) {
            wmma::fragment<wmma::matrix_a, 16, 16, 16, __half, wmma::row_major> af[4];
            wmma::fragment<wmma::matrix_b, 16, 16, 16, __half, wmma::col_major> bh[2], bl[2];
            #pragma unroll
            for (int i = 0; i < 4; i++)
                wmma::load_matrix_sync(af[i], &sA[(wm + i*16)*LDT + ks*16], LDT);
            #pragma unroll
            for (int j = 0; j < 2; j++) {
                wmma::load_matrix_sync(bh[j], &sBh[(wn + j*16)*LDT + ks*16], LDT);
                wmma::load_matrix_sync(bl[j], &sBl[(wn + j*16)*LDT + ks*16], LDT);
            }
            #pragma unroll
            for (int i = 0; i < 4; i++)
                #pragma unroll
                for (int j = 0; j < 2; j++) {
                    wmma::mma_sync(acc[i][j], af[i], bh[j], acc[i][j]);
                    wmma::mma_sync(acc[i][j], af[i], bl[j], acc[i][j]);
                }
        }
        __syncthreads();   // all warps done with buf before it is reloaded (chunk c+2)
    }

    // ---- epilogue: frags -> smem -> outputs ----
    #pragma unroll
    for (int i = 0; i < 4; i++)
        #pragma unroll
        for (int j = 0; j < 2; j++)
            wmma::store_matrix_sync(&sC[(wm + i*16)*LDC + wn + j*16], acc[i][j], LDC,
                                    wmma::mem_row_major);
    __syncthreads();
    float* Cb = C ? C + (long long)b*sCb : nullptr;
    for (int j = 0; j < 64; j++) {
        int lin = tid + j*256;                // 16384 = 128x128
        int row = lin >> 7, col = lin & 127;
        int gm = m0 + row, gn = n0 + col;
        if (gm >= Mrows) continue;
        float v = 0.f;
        if (gn < N) {
            v = sC[row*LDC + col];
            if (bias) v += bias[gn];
            if (act)  v = (v >= 0.f) ? v : 0.1f*v;
            if (Cb) Cb[(long long)gm*Nc + gn] = v;
        }
        if (Ch && gn < NcH)
            Ch[sCHb*b + (long long)gm*NcH + gn] = __float2half(v);
    }
}

// ---------------- fp32 tiled GEMM (small matrices only) ----------------
#define BM 64
#define BN 64
#define BK 16
__global__ void gemm_kernel(const float* __restrict__ A, const float* __restrict__ B,
                            const float* __restrict__ bias,
                            const float* __restrict__ gate, int gateK,
                            const float* __restrict__ resid,
                            float* __restrict__ C,
                            int M, int K, int N,
                            long long sAb, long long sBb, long long sCb,
                            int act, int accum)
{
    int b = blockIdx.z;
    A += (long long)b * sAb;
    B += (long long)b * sBb;
    C += (long long)b * sCb;
    const float* gt = gate ? (gate + (long long)b * gateK) : nullptr;

    __shared__ float As[BK][BM+1];
    __shared__ float Bs[BK][BN+1];

    int tid = threadIdx.x;
    int tx = tid & 15, ty = tid >> 4;
    int m0 = blockIdx.y * BM, n0 = blockIdx.x * BN;

    float acc[4][4];
    #pragma unroll
    for (int i = 0; i < 4; i++)
        #pragma unroll
        for (int j = 0; j < 4; j++) acc[i][j] = 0.f;

    for (int k0 = 0; k0 < K; k0 += BK) {
        #pragma unroll
        for (int l = 0; l < 4; l++) {
            int i = tid + l*256;
            int ar = i >> 4, ac = i & 15;
            int gm = m0 + ar, gk = k0 + ac;
            float vv = 0.f;
            if (gm < M && gk < K) {
                vv = A[(long long)gm*K + gk];
                if (gt) vv *= gt[gk];
            }
            As[ac][ar] = vv;
        }
        #pragma unroll
        for (int l = 0; l < 4; l++) {
            int i = tid + l*256;
            int br = i >> 6, bc = i & 63;
            int gk = k0 + br, gn = n0 + bc;
            Bs[br][bc] = (gk < K && gn < N) ? B[(long long)gk*N + gn] : 0.f;
        }
        __syncthreads();
        #pragma unroll
        for (int kk = 0; kk < BK; kk++) {
            float a[4], bb[4];
            #pragma unroll
            for (int i = 0; i < 4; i++) a[i] = As[kk][ty*4+i];
            #pragma unroll
            for (int j = 0; j < 4; j++) bb[j] = Bs[kk][tx*4+j];
            #pragma unroll
            for (int i = 0; i < 4; i++)
                #pragma unroll
                for (int j = 0; j < 4; j++)
                    acc[i][j] += a[i]*bb[j];
        }
        __syncthreads();
    }

    #pragma unroll
    for (int i = 0; i < 4; i++) {
        int gm = m0 + ty*4 + i;
        if (gm >= M) continue;
        #pragma unroll
        for (int j = 0; j < 4; j++) {
            int gn = n0 + tx*4 + j;
            if (gn >= N) continue;
            float vv = acc[i][j];
            if (bias) vv += bias[gn];
            if (act == 1) vv = (vv >= 0.f) ? vv : 0.1f*vv;
            if (resid) vv += resid[(long long)gm*N + gn];
            long long idx = (long long)gm*N + gn;
            if (accum) vv += C[idx];
            C[idx] = vv;
        }
    }
}

// ---------------- column means (partial over 250-row chunks) ----------------
__global__ void mean_part_kernel(const float* __restrict__ X, float* __restrict__ part, int C)
{
    int b = blockIdx.y, ch = blockIdx.x;
    int c = threadIdx.x;
    if (c >= C) return;
    const float* p = X + ((long long)b*NBASE + ch*250)*C + c;
    float s = 0.f;
    for (int r = 0; r < 250; r++) s += p[(long long)r*C];
    part[((long long)b*32 + ch)*C + c] = s;
}

__global__ void avg_kernel(const float* __restrict__ pv, const float* __restrict__ ps,
                           float* __restrict__ avg)
{
    int b = blockIdx.x, c = threadIdx.x;
    if (c < FEAT) {
        float s = 0.f;
        for (int ch = 0; ch < 32; ch++) s += pv[((long long)b*32+ch)*FEAT + c];
        avg[b*(FEAT+SEM) + c] = s * (1.0f/NBASE);
    } else if (c < FEAT + SEM) {
        int cc = c - FEAT;
        float s = 0.f;
        for (int ch = 0; ch < 32; ch++) s += ps[((long long)b*32+ch)*SEM + cc];
        avg[b*(FEAT+SEM) + FEAT + cc] = s * (1.0f/NBASE);
    }
}

__global__ void gate_kernel(const float* __restrict__ avg, const float* __restrict__ W,
                            const float* __restrict__ bias, float* __restrict__ gate, int N)
{
    int b = blockIdx.x, j = threadIdx.x;
    __shared__ float av[FEAT+SEM];
    for (int i = threadIdx.x; i < FEAT+SEM; i += blockDim.x) av[i] = avg[b*(FEAT+SEM) + i];
    __syncthreads();
    if (j < N) {
        float s = bias[j];
        for (int k = 0; k < FEAT+SEM; k++) s += av[k]*W[(long long)k*N + j];
        gate[b*N + j] = 1.f + 1.f/(1.f + expf(-s));
    }
}

// ---------------- attention scores ----------------
__global__ void attn_kernel(const float* __restrict__ ktot, const float* __restrict__ qtot,
                            float* __restrict__ score)
{
    int b = blockIdx.y;
    int n0 = blockIdx.x * 32;
    __shared__ float qs[NWAY][FEAT];
    __shared__ float ks[32][33];
    const float* q = qtot + (long long)b*NWAY*FEAT;
    for (int i = threadIdx.x; i < NWAY*FEAT; i += 256) qs[i>>9][i&511] = q[i];
    int r  = threadIdx.x & 31;
    int wg = threadIdx.x >> 5;
    float acc0 = 0.f, acc1 = 0.f;
    const float* kb = ktot + ((long long)b*NBASE + n0)*FEAT;
    for (int k0 = 0; k0 < FEAT; k0 += 32) {
        __syncthreads();
        for (int i = threadIdx.x; i < 32*32; i += 256) {
            int rr = i >> 5, cc = i & 31;
            ks[rr][cc] = kb[(long long)rr*FEAT + k0 + cc];
        }
        __syncthreads();
        #pragma unroll
        for (int kk = 0; kk < 32; kk++) {
            float kv = ks[r][kk];
            acc0 += kv * qs[2*wg  ][k0+kk];
            acc1 += kv * qs[2*wg+1][k0+kk];
        }
    }
    score[((long long)b*NWAY + 2*wg  )*NBASE + n0 + r] = acc0 * INV_TEMP;
    score[((long long)b*NWAY + 2*wg+1)*NBASE + n0 + r] = acc1 * INV_TEMP;
}

// ---------------- softmax ----------------
__global__ void softmax_kernel(const float* __restrict__ score, float* __restrict__ attn)
{
    int row = blockIdx.x;
    const float* s = score + (long long)row*NBASE;
    float* a = attn + (long long)row*NBASE;
    __shared__ float red[256];
    float mx = -1e30f;
    for (int i = threadIdx.x; i < NBASE; i += 256) mx = fmaxf(mx, s[i]);
    red[threadIdx.x] = mx; __syncthreads();
    for (int st = 128; st > 0; st >>= 1) {
        if (threadIdx.x < st) red[threadIdx.x] = fmaxf(red[threadIdx.x], red[threadIdx.x+st]);
        __syncthreads();
    }
    mx = red[0]; __syncthreads();
    float sum = 0.f;
    for (int i = threadIdx.x; i < NBASE; i += 256) {
        float e = expf(s[i] - mx);
        a[i] = e;
        sum += e;
    }
    red[threadIdx.x] = sum; __syncthreads();
    for (int st = 128; st > 0; st >>= 1) {
        if (threadIdx.x < st) red[threadIdx.x] += red[threadIdx.x+st];
        __syncthreads();
    }
    float inv = 1.f/red[0];
    for (int i = threadIdx.x; i < NBASE; i += 256) a[i] *= inv;
}

// ---------------- attn @ v, deterministic split-K ----------------
__global__ void av_partial_kernel(const float* __restrict__ attn, const float* __restrict__ v,
                                  float* __restrict__ part)
{
    int b  = blockIdx.x;
    int ch = blockIdx.y;
    int n0 = ch * 320;
    __shared__ float as[NWAY][32];
    int c0 = threadIdx.x;
    float acc[NWAY][2];
    #pragma unroll
    for (int w = 0; w < NWAY; w++) { acc[w][0] = 0.f; acc[w][1] = 0.f; }

    for (int nb = 0; nb < 320; nb += 32) {
        __syncthreads();
        for (int i = threadIdx.x; i < NWAY*32; i += 256) {
            int w = i >> 5, nn = i & 31;
            as[w][nn] = attn[((long long)b*NWAY + w)*NBASE + n0 + nb + nn];
        }
        __syncthreads();
        for (int nn = 0; nn < 32; nn++) {
            const float* vr = v + ((long long)b*NBASE + n0 + nb + nn)*FEAT;
            float v0 = vr[c0], v1 = vr[c0+256];
            #pragma unroll
            for (int w = 0; w < NWAY; w++) {
                acc[w][0] += as[w][nn]*v0;
                acc[w][1] += as[w][nn]*v1;
            }
        }
    }
    #pragma unroll
    for (int w = 0; w < NWAY; w++) {
        part[(((long long)b*25 + ch)*NWAY + w)*FEAT + c0      ] = acc[w][0];
        part[(((long long)b*25 + ch)*NWAY + w)*FEAT + c0 + 256] = acc[w][1];
    }
}

__global__ void av_reduce_kernel(const float* __restrict__ part, float* __restrict__ outpre)
{
    long long i = (long long)blockIdx.x*256 + threadIdx.x;
    int c = i & 511;
    long long bw = i >> 9;
    int w = bw & 15;
    int b = (int)(bw >> 4);
    float s = 0.f;
    for (int ch = 0; ch < 25; ch++)
        s += part[(((long long)b*25 + ch)*NWAY + w)*FEAT + c];
    outpre[i] = s;
}

// ---------------- host ----------------
extern "C" void kernel_launch(void* const* d_in, const int* in_sizes, int n_in,
                              void* d_out, int out_size)
{
    const float* support_feat  = (const float*)d_in[0];
    const float* base_weights  = (const float*)d_in[1];
    const float* support_seman = (const float*)d_in[2];
    const float* base_seman    = (const float*)d_in[3];
    const float* map_w1 = (const float*)d_in[4];
    const float* map_b1 = (const float*)d_in[5];
    const float* map_w2 = (const float*)d_in[6];
    const float* map_b2 = (const float*)d_in[7];
    const float* visfuse_w = (const float*)d_in[8];
    const float* visfuse_b = (const float*)d_in[9];
    const float* semfuse_w = (const float*)d_in[10];
    const float* semfuse_b = (const float*)d_in[11];
    const float* w_qs = (const float*)d_in[12];
    const float* w_ks = (const float*)d_in[13];
    const float* w_vs = (const float*)d_in[14];
    const float* w_qs_sem = (const float*)d_in[15];
    const float* w_ks_sem = (const float*)d_in[16];
    const float* fc_w = (const float*)d_in[17];

    float *calib, *ktot, *v, *suph, *supcalib, *qtot;
    float *meanv, *means, *avg, *gv, *gs, *attn, *part, *outpre, *score_sc, *out_sc;
    cudaGetSymbolAddress((void**)&calib, g_calib);
    cudaGetSymbolAddress((void**)&ktot, g_ktot);
    cudaGetSymbolAddress((void**)&v, g_v);
    cudaGetSymbolAddress((void**)&suph, g_suph);
    cudaGetSymbolAddress((void**)&supcalib, g_supcalib);
    cudaGetSymbolAddress((void**)&qtot, g_qtot);
    cudaGetSymbolAddress((void**)&meanv, g_meanv);
    cudaGetSymbolAddress((void**)&means, g_means);
    cudaGetSymbolAddress((void**)&avg, g_avg);
    cudaGetSymbolAddress((void**)&gv, g_gv);
    cudaGetSymbolAddress((void**)&gs, g_gs);
    cudaGetSymbolAddress((void**)&attn, g_attn);
    cudaGetSymbolAddress((void**)&part, g_part);
    cudaGetSymbolAddress((void**)&outpre, g_outpre);
    cudaGetSymbolAddress((void**)&score_sc, g_score_scratch);
    cudaGetSymbolAddress((void**)&out_sc, g_out_scratch);

    __half *wvsh, *wvsl, *w1h, *w1l, *w2h, *w2l, *wksgh, *wksgl, *wkssgh, *wkssgl;
    cudaGetSymbolAddress((void**)&wvsh, g_wvs_h);     cudaGetSymbolAddress((void**)&wvsl, g_wvs_l);
    cudaGetSymbolAddress((void**)&w1h, g_w1_h);       cudaGetSymbolAddress((void**)&w1l, g_w1_l);
    cudaGetSymbolAddress((void**)&w2h, g_w2_h);       cudaGetSymbolAddress((void**)&w2l, g_w2_l);
    cudaGetSymbolAddress((void**)&wksgh, g_wksg_h);   cudaGetSymbolAddress((void**)&wksgl, g_wksg_l);
    cudaGetSymbolAddress((void**)&wkssgh, g_wkssg_h); cudaGetSymbolAddress((void**)&wkssgl, g_wkssg_l);

    __half *bsmh, *hhh, *bwh, *calh;
    cudaGetSymbolAddress((void**)&bsmh, g_bsm_h);
    cudaGetSymbolAddress((void**)&hhh, g_h_h);
    cudaGetSymbolAddress((void**)&bwh, g_bw_h);
    cudaGetSymbolAddress((void**)&calh, g_cal_h);

    // output layout handling: reference returns (out, attn_score)
    const int OUT_N = NB*NWAY*FEAT;
    const int SC_N  = NB*NWAY*NBASE;
    float* out_ptr   = (float*)d_out;
    float* score_ptr = score_sc;
    if (out_size >= OUT_N + SC_N) {
        out_ptr = (float*)d_out;
        score_ptr = (float*)d_out + OUT_N;
    } else if (out_size == SC_N) {
        out_ptr = out_sc;
        score_ptr = (float*)d_out;
    }

    // dynamic smem: max(2 stages x 30KB, epilogue 69,632B)
    const int SMEMB = 128*LDC*4;   // 69,632
    cudaFuncSetAttribute(wmma_gemm3, cudaFuncAttributeMaxDynamicSharedMemorySize, SMEMB);

    const long long sBSM = (long long)NBASE*SEMP;
    const long long sBW  = (long long)NBASE*FEAT;

    // 0) shared-weight prep (fp16 hi/lo, transposed)
    split_w_kernel<<<(512*512+255)/256, 256>>>(w_vs, 512, 512, wvsh, wvsl, 512, 512);
    split_w_kernel<<<(384*SEMP+255)/256, 256>>>(map_w1, SEM, SEM, w1h, w1l, SEMP, 384);
    split_w_kernel<<<(384*SEMP+255)/256, 256>>>(map_w2, SEM, SEM, w2h, w2l, SEMP, 384);

    // 0b) activation converts (fp16, no gates anywhere)
    conv_a_kernel<<<dim3((NBASE*SEMP+255)/256, NB), 256>>>(base_seman, NBASE, SEM, SEMP,
        (long long)NBASE*SEM, bsmh);
    conv_a_kernel<<<dim3((NBASE*FEAT+255)/256, NB), 256>>>(base_weights, NBASE, FEAT, FEAT,
        (long long)NBASE*FEAT, bwh);

    // 1) map_sem: layer1 -> h (fp16 only, with LeakyReLU), layer2 -> calib fp32 + fp16
    wmma_gemm3<<<dim3(3, 63, NB), 256, SMEMB>>>(
        bsmh, w1h, w1l, SEMP, sBSM, 0,
        nullptr, nullptr, nullptr, 0, 0, 0,
        NBASE, SEM, 0, 0, map_b1, nullptr, 1,
        hhh, sBSM, SEMP);
    wmma_gemm3<<<dim3(3, 63, NB), 256, SMEMB>>>(
        hhh, w2h, w2l, SEMP, sBSM, 0,
        nullptr, nullptr, nullptr, 0, 0, 0,
        NBASE, SEM, SEM, (long long)NBASE*SEM, map_b2, calib, 0,
        calh, sBSM, SEMP);

    // 2) v = bw @ w_vs (independent of gates)
    wmma_gemm3<<<dim3(4, 63, NB), 256, SMEMB>>>(
        bwh, wvsh, wvsl, FEAT, sBW, 0,
        nullptr, nullptr, nullptr, 0, 0, 0,
        NBASE, FEAT, FEAT, sBW, nullptr, v, 0,
        nullptr, 0, 0);

    // 3) support-side small fp32 chain (independent)
    gemm_kernel<<<dim3(5, 2, 1), 256>>>(support_seman, map_w1, map_b1, nullptr, 0, nullptr,
                                        suph, NB*NWAY, SEM, SEM, 0, 0, 0, 1, 0);
    gemm_kernel<<<dim3(5, 2, 1), 256>>>(suph, map_w2, map_b2, nullptr, 0, nullptr,
                                        supcalib, NB*NWAY, SEM, SEM, 0, 0, 0, 0, 0);
    gemm_kernel<<<dim3(8, 2, 1), 256>>>(support_feat, w_qs, nullptr, nullptr, 0, nullptr,
                                        qtot, NB*NWAY, FEAT, FEAT, 0, 0, 0, 0, 0);
    gemm_kernel<<<dim3(8, 2, 1), 256>>>(supcalib, w_qs_sem, nullptr, nullptr, 0, nullptr,
                                        qtot, NB*NWAY, SEM, FEAT, 0, 0, 0, 0, 1);

    // 4) means over base classes -> avg -> gates
    mean_part_kernel<<<dim3(32, NB), 512>>>(base_weights, meanv, FEAT);
    mean_part_kernel<<<dim3(32, NB), 512>>>(calib, means, SEM);
    avg_kernel<<<NB, 1024>>>(meanv, means, avg);
    gate_kernel<<<NB, 512>>>(avg, visfuse_w, visfuse_b, gv, FEAT);
    gate_kernel<<<NB, 512>>>(avg, semfuse_w, semfuse_b, gs, SEM);

    // 4b) fold gates into per-batch weights (tiny)
    scale_split_w_kernel<<<dim3((512*512+255)/256, NB), 256>>>(w_ks, FEAT, FEAT, gv,
        wksgh, wksgl, 512, 512);
    scale_split_w_kernel<<<dim3((512*SEMP+255)/256, NB), 256>>>(w_ks_sem, SEM, FEAT, gs,
        wkssgh, wkssgl, SEMP, 512);

    // 5) ktot = bw @ (gv*w_ks) + calib @ (gs*w_ks_sem) — single fused K-sweep (K=512+320)
    wmma_gemm3<<<dim3(4, 63, NB), 256, SMEMB>>>(
        bwh, wksgh, wksgl, FEAT, sBW, (long long)512*512,
        calh, wkssgh, wkssgl, SEMP, sBSM, (long long)512*SEMP,
        NBASE, FEAT, FEAT, sBW, nullptr, ktot, 0,
        nullptr, 0, 0);

    // 6) scores, softmax, attn@v, final proj + residual
    attn_kernel<<<dim3(NBASE/32, NB), 256>>>(ktot, qtot, score_ptr);
    softmax_kernel<<<NB*NWAY, 256>>>(score_ptr, attn);
    av_partial_kernel<<<dim3(NB, 25), 256>>>(attn, v, part);
    av_reduce_kernel<<<256, 256>>>(part, outpre);
    gemm_kernel<<<dim3(8, 2, 1), 256>>>(outpre, fc_w, nullptr, nullptr, 0, support_feat,
                                        out_ptr, NB*NWAY, FEAT, FEAT, 0, 0, 0, 0, 0);
}

// round 16
// speedup vs baseline: 3.4174x; 1.2414x over previous
#include <cuda_runtime.h>
#include <cuda_fp16.h>
#include <mma.h>
#include <math.h>
#include <stdint.h>

using namespace nvcuda;

// ---------------- problem constants ----------------
#define NB   8
#define NWAY 16
#define NBASE 8000
#define FEAT 512
#define SEM  300
#define SEMP 320                  // padded SEM (mult of 64)
#define INV_TEMP (1.0f/22.62741699796952f)

// ---------------- device scratch (no allocs allowed) ----------------
__device__ float g_calib[NB*NBASE*SEM];    // calibrated base_seman (fp32, for means)
__device__ float g_ktot[NB*NBASE*FEAT];    // fused keys
__device__ float g_v[NB*NBASE*FEAT];       // values
__device__ float g_suph[NB*NWAY*SEM];
__device__ float g_supcalib[NB*NWAY*SEM];
__device__ float g_qtot[NB*NWAY*FEAT];
__device__ float g_meanv[NB*32*FEAT];
__device__ float g_means[NB*32*SEM];
__device__ float g_avg[NB*(FEAT+SEM)];
__device__ float g_gv[NB*FEAT];
__device__ float g_gs[NB*SEM];
__device__ float g_attn[NB*NWAY*NBASE];
__device__ float g_part[NB*25*NWAY*FEAT];
__device__ float g_outpre[NB*NWAY*FEAT];
__device__ float g_score_scratch[NB*NWAY*NBASE];
__device__ float g_out_scratch[NB*NWAY*FEAT];

// map_sem weights (hi+lo, error-compounding chain), transposed [n, Kp]
__device__ __align__(256) __half g_w1_h[384*SEMP], g_w1_l[384*SEMP];
__device__ __align__(256) __half g_w2_h[384*SEMP], g_w2_l[384*SEMP];
// hi-only weights
__device__ __align__(256) __half g_wvs_h[512*512];
__device__ __align__(256) __half g_wksg_h[NB*512*512];    // per-batch gate-scaled
__device__ __align__(256) __half g_wkssg_h[NB*512*SEMP];  // per-batch gate-scaled

// fp16 activations (hi only), [b, m, Kp]
__device__ __align__(256) __half g_bsm_h[NB*NBASE*SEMP];  // base_seman
__device__ __align__(256) __half g_h_h[NB*NBASE*SEMP];    // map_sem layer1 out
__device__ __align__(256) __half g_bw_h[NB*NBASE*FEAT];   // base_weights
__device__ __align__(256) __half g_cal_h[NB*NBASE*SEMP];  // calib

__device__ __forceinline__ uint32_t smem_cast(const void* p) {
    uint32_t a;
    asm("{ .reg .u64 t; cvta.to.shared.u64 t, %1; cvt.u32.u64 %0, t; }" : "=r"(a) : "l"(p));
    return a;
}
#define CP16(dst, src) asm volatile("cp.async.cg.shared.global [%0], [%1], 16;" :: "r"(dst), "l"(src))
#define CPCOMMIT()     asm volatile("cp.async.commit_group;")
#define CPWAIT(n)      asm volatile("cp.async.wait_group %0;" :: "n"(n))

// ========== weight prep: transpose + fp16 hi/lo split ==========
__global__ void split_w_kernel(const float* __restrict__ W, int K, int N,
                               __half* __restrict__ Th, __half* __restrict__ Tl,
                               int Kp, int Nr)
{
    long long i = (long long)blockIdx.x*256 + threadIdx.x;
    if (i >= (long long)Nr*Kp) return;
    int n = (int)(i / Kp), k = (int)(i % Kp);
    float v = (k < K && n < N) ? W[(long long)k*N + n] : 0.f;
    __half h = __float2half(v);
    Th[i] = h;
    Tl[i] = __float2half(v - __half2float(h));
}

// ========== weight prep: transpose, fp16 hi only ==========
__global__ void conv_w_kernel(const float* __restrict__ W, int K, int N,
                              __half* __restrict__ Th, int Kp, int Nr)
{
    long long i = (long long)blockIdx.x*256 + threadIdx.x;
    if (i >= (long long)Nr*Kp) return;
    int n = (int)(i / Kp), k = (int)(i % Kp);
    float v = (k < K && n < N) ? W[(long long)k*N + n] : 0.f;
    Th[i] = __float2half(v);
}

// ========== gate-scaled weight prep: W'[b][n][k] = gate[b][k]*W[k][n], hi only ==========
__global__ void scale_conv_w_kernel(const float* __restrict__ W, int K, int N,
                                    const float* __restrict__ gate,
                                    __half* __restrict__ Th, int Kp, int Nr)
{
    int b = blockIdx.y;
    long long i = (long long)blockIdx.x*256 + threadIdx.x;
    if (i >= (long long)Nr*Kp) return;
    int n = (int)(i / Kp), k = (int)(i % Kp);
    float v = (k < K && n < N) ? W[(long long)k*N + n] * gate[(long long)b*K + k] : 0.f;
    Th[(long long)b*Nr*Kp + i] = __float2half(v);
}

// ========== activation converts ==========
// 8 elems/thread, K == Kp, K % 8 == 0 (FEAT case)
__global__ void conv_a8_kernel(const float* __restrict__ X, int M, int K,
                               long long sXb, __half* __restrict__ H)
{
    int b = blockIdx.y;
    long long i = (long long)blockIdx.x*256 + threadIdx.x;       // elem8 index
    int perRow = K >> 3;
    if (i >= (long long)M*perRow) return;
    int m = (int)(i / perRow), kq = (int)(i % perRow) * 8;
    const float* src = X + (long long)b*sXb + (long long)m*K + kq;
    float4 v0 = *reinterpret_cast<const float4*>(src);
    float4 v1 = *reinterpret_cast<const float4*>(src + 4);
    __half2 h[4];
    h[0] = __floats2half2_rn(v0.x, v0.y);
    h[1] = __floats2half2_rn(v0.z, v0.w);
    h[2] = __floats2half2_rn(v1.x, v1.y);
    h[3] = __floats2half2_rn(v1.z, v1.w);
    *reinterpret_cast<uint4*>(H + (long long)b*M*K + (long long)m*K + kq)
        = *reinterpret_cast<uint4*>(h);
}

// 2 elems/thread, K even, Kp even (SEM case)
__global__ void conv_a2_kernel(const float* __restrict__ X, int M, int K, int Kp,
                               long long sXb, __half* __restrict__ H)
{
    int b = blockIdx.y;
    long long i = (long long)blockIdx.x*256 + threadIdx.x;       // pair index
    int perRow = Kp >> 1;
    if (i >= (long long)M*perRow) return;
    int m = (int)(i / perRow), k = (int)(i % perRow) * 2;
    float a = 0.f, c = 0.f;
    if (k < K) {
        const float* src = X + (long long)b*sXb + (long long)m*K + k;
        a = src[0]; c = src[1];
    }
    *reinterpret_cast<__half2*>(H + (long long)b*M*Kp + (long long)m*Kp + k)
        = __floats2half2_rn(a, c);
}

// ================= WMMA fp16 GEMM, dual-K-source, cp.async double-buffered ========
// C[b] = act( A1[b] @ B1[b]^T + A2[b] @ B2[b]^T + bias )
// A fp16 [M, Kp]; B fp16 [n, Kp] hi (+lo if USE_LO).
// Block tile 128x128, 8 warps as 2(m)x4(n), warp tile 64x32, K-chunk 32.
#define LDT 40     // smem tile leading dim in halves (32 + 8 pad, 80B rows)
#define LDC 136    // smem epilogue leading dim in f32
template<bool USE_LO>
__global__ void __launch_bounds__(256, 2) wmma_gemm3(
    const __half* __restrict__ A1, const __half* __restrict__ B1h, const __half* __restrict__ B1l,
    int K1p, long long sA1b, long long sB1b,
    const __half* __restrict__ A2, const __half* __restrict__ B2h, const __half* __restrict__ B2l,
    int K2p, long long sA2b, long long sB2b,
    int Mrows, int N, int Nc, long long sCb,
    const float* __restrict__ bias,
    float* __restrict__ C, int act,
    __half* __restrict__ Ch, long long sCHb, int NcH)
{
    extern __shared__ char smem[];
    const int NMAT = USE_LO ? 3 : 2;
    const int STAGE = NMAT*128*LDT;           // halves per stage
    __half* s0 = (__half*)smem;
    float* sC = (float*)smem;

    int b = blockIdx.z;
    int m0 = blockIdx.y*128, n0 = blockIdx.x*128;
    int tid = threadIdx.x, wid = tid >> 5;
    int wm = (wid & 1)*64, wn = (wid >> 1)*32;

    // load assignment: 512 16B-segs per matrix, 2 per thread
    int r0 = tid >> 1;            // rows 0..127 (2 segs each)
    int q0 = (tid & 1)*2;         // seg cols {0,1} or {2,3}
    int am0 = m0 + r0; if (am0 >= Mrows) am0 = Mrows - 1;

    auto load_chunk = [&](int c, int buf) {
        int k0 = c*32;
        const __half *Ap, *Bph, *Bpl = nullptr;
        int Kp;
        if (k0 < K1p) {
            Ap  = A1 + (long long)b*sA1b + k0;
            Bph = B1h + (long long)b*sB1b + k0;
            if (USE_LO) Bpl = B1l + (long long)b*sB1b + k0;
            Kp = K1p;
        } else {
            int k2 = k0 - K1p;
            Ap  = A2 + (long long)b*sA2b + k2;
            Bph = B2h + (long long)b*sB2b + k2;
            if (USE_LO) Bpl = B2l + (long long)b*sB2b + k2;
            Kp = K2p;
        }
        __half* st = s0 + buf*STAGE;
        uint32_t offA  = smem_cast(&st[r0*LDT + q0*8]);
        uint32_t offBh = smem_cast(&st[128*LDT + r0*LDT + q0*8]);
        const __half* aS  = Ap  + (long long)am0*Kp + q0*8;
        const __half* bSh = Bph + (long long)(n0 + r0)*Kp + q0*8;
        CP16(offA,       aS);
        CP16(offA  + 16, aS  + 8);
        CP16(offBh,      bSh);
        CP16(offBh + 16, bSh + 8);
        if (USE_LO) {
            uint32_t offBl = smem_cast(&st[2*128*LDT + r0*LDT + q0*8]);
            const __half* bSl = Bpl + (long long)(n0 + r0)*Kp + q0*8;
            CP16(offBl,      bSl);
            CP16(offBl + 16, bSl + 8);
        }
    };

    wmma::fragment<wmma::accumulator, 16, 16, 16, float> acc[4][2];
    #pragma unroll
    for (int i = 0; i < 4; i++)
        #pragma unroll
        for (int j = 0; j < 2; j++) wmma::fill_fragment(acc[i][j], 0.f);

    const int nc = (K1p + K2p)/32;
    load_chunk(0, 0);
    CPCOMMIT();
    for (int c = 0; c < nc; c++) {
        int buf = c & 1;
        CPWAIT(0);
        __syncthreads();
        if (c+1 < nc) { load_chunk(c+1, buf ^ 1); CPCOMMIT(); }
        __half* st = s0 + buf*STAGE;
        __half* sA  = st;
        __half* sBh = st + 128*LDT;
        __half* sBl = st + 2*128*LDT;
        #pragma unroll
        for (int ks = 0; ks < 2; ks++) {
            wmma::fragment<wmma::matrix_a, 16, 16, 16, __half, wmma::row_major> af[4];
            wmma::fragment<wmma::matrix_b, 16, 16, 16, __half, wmma::col_major> bh[2];
            #pragma unroll
            for (int i = 0; i < 4; i++)
                wmma::load_matrix_sync(af[i], &sA[(wm + i*16)*LDT + ks*16], LDT);
            #pragma unroll
            for (int j = 0; j < 2; j++)
                wmma::load_matrix_sync(bh[j], &sBh[(wn + j*16)*LDT + ks*16], LDT);
            #pragma unroll
            for (int i = 0; i < 4; i++)
                #pragma unroll
                for (int j = 0; j < 2; j++)
                    wmma::mma_sync(acc[i][j], af[i], bh[j], acc[i][j]);
            if (USE_LO) {
                wmma::fragment<wmma::matrix_b, 16, 16, 16, __half, wmma::col_major> bl[2];
                #pragma unroll
                for (int j = 0; j < 2; j++)
                    wmma::load_matrix_sync(bl[j], &sBl[(wn + j*16)*LDT + ks*16], LDT);
                #pragma unroll
                for (int i = 0; i < 4; i++)
                    #pragma unroll
                    for (int j = 0; j < 2; j++)
                        wmma::mma_sync(acc[i][j], af[i], bl[j], acc[i][j]);
            }
        }
        __syncthreads();   // all warps done with buf before it is reloaded (chunk c+2)
    }

    // ---- epilogue: frags -> smem -> outputs ----
    #pragma unroll
    for (int i = 0; i < 4; i++)
        #pragma unroll
        for (int j = 0; j < 2; j++)
            wmma::store_matrix_sync(&sC[(wm + i*16)*LDC + wn + j*16], acc[i][j], LDC,
                                    wmma::mem_row_major);
    __syncthreads();
    float* Cb = C ? C + (long long)b*sCb : nullptr;
    for (int j = 0; j < 64; j++) {
        int lin = tid + j*256;                // 16384 = 128x128
        int row = lin >> 7, col = lin & 127;
        int gm = m0 + row, gn = n0 + col;
        if (gm >= Mrows) continue;
        float v = 0.f;
        if (gn < N) {
            v = sC[row*LDC + col];
            if (bias) v += bias[gn];
            if (act)  v = (v >= 0.f) ? v : 0.1f*v;
            if (Cb) Cb[(long long)gm*Nc + gn] = v;
        }
        if (Ch && gn < NcH)
            Ch[sCHb*b + (long long)gm*NcH + gn] = __float2half(v);
    }
}

// ---------------- fp32 tiled GEMM (small matrices only) ----------------
#define BM 64
#define BN 64
#define BK 16
__global__ void gemm_kernel(const float* __restrict__ A, const float* __restrict__ B,
                            const float* __restrict__ bias,
                            const float* __restrict__ gate, int gateK,
                            const float* __restrict__ resid,
                            float* __restrict__ C,
                            int M, int K, int N,
                            long long sAb, long long sBb, long long sCb,
                            int act, int accum)
{
    int b = blockIdx.z;
    A += (long long)b * sAb;
    B += (long long)b * sBb;
    C += (long long)b * sCb;
    const float* gt = gate ? (gate + (long long)b * gateK) : nullptr;

    __shared__ float As[BK][BM+1];
    __shared__ float Bs[BK][BN+1];

    int tid = threadIdx.x;
    int tx = tid & 15, ty = tid >> 4;
    int m0 = blockIdx.y * BM, n0 = blockIdx.x * BN;

    float acc[4][4];
    #pragma unroll
    for (int i = 0; i < 4; i++)
        #pragma unroll
        for (int j = 0; j < 4; j++) acc[i][j] = 0.f;

    for (int k0 = 0; k0 < K; k0 += BK) {
        #pragma unroll
        for (int l = 0; l < 4; l++) {
            int i = tid + l*256;
            int ar = i >> 4, ac = i & 15;
            int gm = m0 + ar, gk = k0 + ac;
            float vv = 0.f;
            if (gm < M && gk < K) {
                vv = A[(long long)gm*K + gk];
                if (gt) vv *= gt[gk];
            }
            As[ac][ar] = vv;
        }
        #pragma unroll
        for (int l = 0; l < 4; l++) {
            int i = tid + l*256;
            int br = i >> 6, bc = i & 63;
            int gk = k0 + br, gn = n0 + bc;
            Bs[br][bc] = (gk < K && gn < N) ? B[(long long)gk*N + gn] : 0.f;
        }
        __syncthreads();
        #pragma unroll
        for (int kk = 0; kk < BK; kk++) {
            float a[4], bb[4];
            #pragma unroll
            for (int i = 0; i < 4; i++) a[i] = As[kk][ty*4+i];
            #pragma unroll
            for (int j = 0; j < 4; j++) bb[j] = Bs[kk][tx*4+j];
            #pragma unroll
            for (int i = 0; i < 4; i++)
                #pragma unroll
                for (int j = 0; j < 4; j++)
                    acc[i][j] += a[i]*bb[j];
        }
        __syncthreads();
    }

    #pragma unroll
    for (int i = 0; i < 4; i++) {
        int gm = m0 + ty*4 + i;
        if (gm >= M) continue;
        #pragma unroll
        for (int j = 0; j < 4; j++) {
            int gn = n0 + tx*4 + j;
            if (gn >= N) continue;
            float vv = acc[i][j];
            if (bias) vv += bias[gn];
            if (act == 1) vv = (vv >= 0.f) ? vv : 0.1f*vv;
            if (resid) vv += resid[(long long)gm*N + gn];
            long long idx = (long long)gm*N + gn;
            if (accum) vv += C[idx];
            C[idx] = vv;
        }
    }
}

// ---------------- column means (partial over 250-row chunks) ----------------
__global__ void mean_part_kernel(const float* __restrict__ X, float* __restrict__ part, int C)
{
    int b = blockIdx.y, ch = blockIdx.x;
    int c = threadIdx.x;
    if (c >= C) return;
    const float* p = X + ((long long)b*NBASE + ch*250)*C + c;
    float s = 0.f;
    for (int r = 0; r < 250; r++) s += p[(long long)r*C];
    part[((long long)b*32 + ch)*C + c] = s;
}

__global__ void avg_kernel(const float* __restrict__ pv, const float* __restrict__ ps,
                           float* __restrict__ avg)
{
    int b = blockIdx.x, c = threadIdx.x;
    if (c < FEAT) {
        float s = 0.f;
        for (int ch = 0; ch < 32; ch++) s += pv[((long long)b*32+ch)*FEAT + c];
        avg[b*(FEAT+SEM) + c] = s * (1.0f/NBASE);
    } else if (c < FEAT + SEM) {
        int cc = c - FEAT;
        float s = 0.f;
        for (int ch = 0; ch < 32; ch++) s += ps[((long long)b*32+ch)*SEM + cc];
        avg[b*(FEAT+SEM) + FEAT + cc] = s * (1.0f/NBASE);
    }
}

__global__ void gate_kernel(const float* __restrict__ avg, const float* __restrict__ W,
                            const float* __restrict__ bias, float* __restrict__ gate, int N)
{
    int b = blockIdx.x, j = threadIdx.x;
    __shared__ float av[FEAT+SEM];
    for (int i = threadIdx.x; i < FEAT+SEM; i += blockDim.x) av[i] = avg[b*(FEAT+SEM) + i];
    __syncthreads();
    if (j < N) {
        float s = bias[j];
        for (int k = 0; k < FEAT+SEM; k++) s += av[k]*W[(long long)k*N + j];
        gate[b*N + j] = 1.f + 1.f/(1.f + expf(-s));
    }
}

// ---------------- attention scores ----------------
__global__ void attn_kernel(const float* __restrict__ ktot, const float* __restrict__ qtot,
                            float* __restrict__ score)
{
    int b = blockIdx.y;
    int n0 = blockIdx.x * 32;
    __shared__ float qs[NWAY][FEAT];
    __shared__ float ks[32][33];
    const float* q = qtot + (long long)b*NWAY*FEAT;
    for (int i = threadIdx.x; i < NWAY*FEAT; i += 256) qs[i>>9][i&511] = q[i];
    int r  = threadIdx.x & 31;
    int wg = threadIdx.x >> 5;
    float acc0 = 0.f, acc1 = 0.f;
    const float* kb = ktot + ((long long)b*NBASE + n0)*FEAT;
    for (int k0 = 0; k0 < FEAT; k0 += 32) {
        __syncthreads();
        for (int i = threadIdx.x; i < 32*32; i += 256) {
            int rr = i >> 5, cc = i & 31;
            ks[rr][cc] = kb[(long long)rr*FEAT + k0 + cc];
        }
        __syncthreads();
        #pragma unroll
        for (int kk = 0; kk < 32; kk++) {
            float kv = ks[r][kk];
            acc0 += kv * qs[2*wg  ][k0+kk];
            acc1 += kv * qs[2*wg+1][k0+kk];
        }
    }
    score[((long long)b*NWAY + 2*wg  )*NBASE + n0 + r] = acc0 * INV_TEMP;
    score[((long long)b*NWAY + 2*wg+1)*NBASE + n0 + r] = acc1 * INV_TEMP;
}

// ---------------- softmax ----------------
__global__ void softmax_kernel(const float* __restrict__ score, float* __restrict__ attn)
{
    int row = blockIdx.x;
    const float* s = score + (long long)row*NBASE;
    float* a = attn + (long long)row*NBASE;
    __shared__ float red[256];
    float mx = -1e30f;
    for (int i = threadIdx.x; i < NBASE; i += 256) mx = fmaxf(mx, s[i]);
    red[threadIdx.x] = mx; __syncthreads();
    for (int st = 128; st > 0; st >>= 1) {
        if (threadIdx.x < st) red[threadIdx.x] = fmaxf(red[threadIdx.x], red[threadIdx.x+st]);
        __syncthreads();
    }
    mx = red[0]; __syncthreads();
    float sum = 0.f;
    for (int i = threadIdx.x; i < NBASE; i += 256) {
        float e = expf(s[i] - mx);
        a[i] = e;
        sum += e;
    }
    red[threadIdx.x] = sum; __syncthreads();
    for (int st = 128; st > 0; st >>= 1) {
        if (threadIdx.x < st) red[threadIdx.x] += red[threadIdx.x+st];
        __syncthreads();
    }
    float inv = 1.f/red[0];
    for (int i = threadIdx.x; i < NBASE; i += 256) a[i] *= inv;
}

// ---------------- attn @ v, deterministic split-K ----------------
__global__ void av_partial_kernel(const float* __restrict__ attn, const float* __restrict__ v,
                                  float* __restrict__ part)
{
    int b  = blockIdx.x;
    int ch = blockIdx.y;
    int n0 = ch * 320;
    __shared__ float as[NWAY][32];
    int c0 = threadIdx.x;
    float acc[NWAY][2];
    #pragma unroll
    for (int w = 0; w < NWAY; w++) { acc[w][0] = 0.f; acc[w][1] = 0.f; }

    for (int nb = 0; nb < 320; nb += 32) {
        __syncthreads();
        for (int i = threadIdx.x; i < NWAY*32; i += 256) {
            int w = i >> 5, nn = i & 31;
            as[w][nn] = attn[((long long)b*NWAY + w)*NBASE + n0 + nb + nn];
        }
        __syncthreads();
        for (int nn = 0; nn < 32; nn++) {
            const float* vr = v + ((long long)b*NBASE + n0 + nb + nn)*FEAT;
            float v0 = vr[c0], v1 = vr[c0+256];
            #pragma unroll
            for (int w = 0; w < NWAY; w++) {
                acc[w][0] += as[w][nn]*v0;
                acc[w][1] += as[w][nn]*v1;
            }
        }
    }
    #pragma unroll
    for (int w = 0; w < NWAY; w++) {
        part[(((long long)b*25 + ch)*NWAY + w)*FEAT + c0      ] = acc[w][0];
        part[(((long long)b*25 + ch)*NWAY + w)*FEAT + c0 + 256] = acc[w][1];
    }
}

__global__ void av_reduce_kernel(const float* __restrict__ part, float* __restrict__ outpre)
{
    long long i = (long long)blockIdx.x*256 + threadIdx.x;
    int c = i & 511;
    long long bw = i >> 9;
    int w = bw & 15;
    int b = (int)(bw >> 4);
    float s = 0.f;
    for (int ch = 0; ch < 25; ch++)
        s += part[(((long long)b*25 + ch)*NWAY + w)*FEAT + c];
    outpre[i] = s;
}

// ---------------- host ----------------
extern "C" void kernel_launch(void* const* d_in, const int* in_sizes, int n_in,
                              void* d_out, int out_size)
{
    const float* support_feat  = (const float*)d_in[0];
    const float* base_weights  = (const float*)d_in[1];
    const float* support_seman = (const float*)d_in[2];
    const float* base_seman    = (const float*)d_in[3];
    const float* map_w1 = (const float*)d_in[4];
    const float* map_b1 = (const float*)d_in[5];
    const float* map_w2 = (const float*)d_in[6];
    const float* map_b2 = (const float*)d_in[7];
    const float* visfuse_w = (const float*)d_in[8];
    const float* visfuse_b = (const float*)d_in[9];
    const float* semfuse_w = (const float*)d_in[10];
    const float* semfuse_b = (const float*)d_in[11];
    const float* w_qs = (const float*)d_in[12];
    const float* w_ks = (const float*)d_in[13];
    const float* w_vs = (const float*)d_in[14];
    const float* w_qs_sem = (const float*)d_in[15];
    const float* w_ks_sem = (const float*)d_in[16];
    const float* fc_w = (const float*)d_in[17];

    float *calib, *ktot, *v, *suph, *supcalib, *qtot;
    float *meanv, *means, *avg, *gv, *gs, *attn, *part, *outpre, *score_sc, *out_sc;
    cudaGetSymbolAddress((void**)&calib, g_calib);
    cudaGetSymbolAddress((void**)&ktot, g_ktot);
    cudaGetSymbolAddress((void**)&v, g_v);
    cudaGetSymbolAddress((void**)&suph, g_suph);
    cudaGetSymbolAddress((void**)&supcalib, g_supcalib);
    cudaGetSymbolAddress((void**)&qtot, g_qtot);
    cudaGetSymbolAddress((void**)&meanv, g_meanv);
    cudaGetSymbolAddress((void**)&means, g_means);
    cudaGetSymbolAddress((void**)&avg, g_avg);
    cudaGetSymbolAddress((void**)&gv, g_gv);
    cudaGetSymbolAddress((void**)&gs, g_gs);
    cudaGetSymbolAddress((void**)&attn, g_attn);
    cudaGetSymbolAddress((void**)&part, g_part);
    cudaGetSymbolAddress((void**)&outpre, g_outpre);
    cudaGetSymbolAddress((void**)&score_sc, g_score_scratch);
    cudaGetSymbolAddress((void**)&out_sc, g_out_scratch);

    __half *wvsh, *w1h, *w1l, *w2h, *w2l, *wksgh, *wkssgh;
    cudaGetSymbolAddress((void**)&wvsh, g_wvs_h);
    cudaGetSymbolAddress((void**)&w1h, g_w1_h);       cudaGetSymbolAddress((void**)&w1l, g_w1_l);
    cudaGetSymbolAddress((void**)&w2h, g_w2_h);       cudaGetSymbolAddress((void**)&w2l, g_w2_l);
    cudaGetSymbolAddress((void**)&wksgh, g_wksg_h);
    cudaGetSymbolAddress((void**)&wkssgh, g_wkssg_h);

    __half *bsmh, *hhh, *bwh, *calh;
    cudaGetSymbolAddress((void**)&bsmh, g_bsm_h);
    cudaGetSymbolAddress((void**)&hhh, g_h_h);
    cudaGetSymbolAddress((void**)&bwh, g_bw_h);
    cudaGetSymbolAddress((void**)&calh, g_cal_h);

    // output layout handling: reference returns (out, attn_score)
    const int OUT_N = NB*NWAY*FEAT;
    const int SC_N  = NB*NWAY*NBASE;
    float* out_ptr   = (float*)d_out;
    float* score_ptr = score_sc;
    if (out_size >= OUT_N + SC_N) {
        out_ptr = (float*)d_out;
        score_ptr = (float*)d_out + OUT_N;
    } else if (out_size == SC_N) {
        out_ptr = out_sc;
        score_ptr = (float*)d_out;
    }

    // dynamic smem: max(stages, epilogue 69,632B)
    const int SMEMB = 128*LDC*4;   // 69,632
    cudaFuncSetAttribute(wmma_gemm3<true>,  cudaFuncAttributeMaxDynamicSharedMemorySize, SMEMB);
    cudaFuncSetAttribute(wmma_gemm3<false>, cudaFuncAttributeMaxDynamicSharedMemorySize, SMEMB);

    const long long sBSM = (long long)NBASE*SEMP;
    const long long sBW  = (long long)NBASE*FEAT;

    // 0) weight prep
    conv_w_kernel<<<(512*512+255)/256, 256>>>(w_vs, 512, 512, wvsh, 512, 512);
    split_w_kernel<<<(384*SEMP+255)/256, 256>>>(map_w1, SEM, SEM, w1h, w1l, SEMP, 384);
    split_w_kernel<<<(384*SEMP+255)/256, 256>>>(map_w2, SEM, SEM, w2h, w2l, SEMP, 384);

    // 0b) activation converts (vectorized)
    conv_a2_kernel<<<dim3((NBASE*(SEMP/2)+255)/256, NB), 256>>>(base_seman, NBASE, SEM, SEMP,
        (long long)NBASE*SEM, bsmh);
    conv_a8_kernel<<<dim3((NBASE*(FEAT/8)+255)/256, NB), 256>>>(base_weights, NBASE, FEAT,
        (long long)NBASE*FEAT, bwh);

    // 1) map_sem (hi+lo weights): layer1 -> h fp16 (LeakyReLU), layer2 -> calib fp32 + fp16
    wmma_gemm3<true><<<dim3(3, 63, NB), 256, SMEMB>>>(
        bsmh, w1h, w1l, SEMP, sBSM, 0,
        nullptr, nullptr, nullptr, 0, 0, 0,
        NBASE, SEM, 0, 0, map_b1, nullptr, 1,
        hhh, sBSM, SEMP);
    wmma_gemm3<true><<<dim3(3, 63, NB), 256, SMEMB>>>(
        hhh, w2h, w2l, SEMP, sBSM, 0,
        nullptr, nullptr, nullptr, 0, 0, 0,
        NBASE, SEM, SEM, (long long)NBASE*SEM, map_b2, calib, 0,
        calh, sBSM, SEMP);

    // 2) v = bw @ w_vs (single-pass fp16)
    wmma_gemm3<false><<<dim3(4, 63, NB), 256, SMEMB>>>(
        bwh, wvsh, nullptr, FEAT, sBW, 0,
        nullptr, nullptr, nullptr, 0, 0, 0,
        NBASE, FEAT, FEAT, sBW, nullptr, v, 0,
        nullptr, 0, 0);

    // 3) support-side small fp32 chain (independent)
    gemm_kernel<<<dim3(5, 2, 1), 256>>>(support_seman, map_w1, map_b1, nullptr, 0, nullptr,
                                        suph, NB*NWAY, SEM, SEM, 0, 0, 0, 1, 0);
    gemm_kernel<<<dim3(5, 2, 1), 256>>>(suph, map_w2, map_b2, nullptr, 0, nullptr,
                                        supcalib, NB*NWAY, SEM, SEM, 0, 0, 0, 0, 0);
    gemm_kernel<<<dim3(8, 2, 1), 256>>>(support_feat, w_qs, nullptr, nullptr, 0, nullptr,
                                        qtot, NB*NWAY, FEAT, FEAT, 0, 0, 0, 0, 0);
    gemm_kernel<<<dim3(8, 2, 1), 256>>>(supcalib, w_qs_sem, nullptr, nullptr, 0, nullptr,
                                        qtot, NB*NWAY, SEM, FEAT, 0, 0, 0, 0, 1);

    // 4) means over base classes -> avg -> gates
    mean_part_kernel<<<dim3(32, NB), 512>>>(base_weights, meanv, FEAT);
    mean_part_kernel<<<dim3(32, NB), 512>>>(calib, means, SEM);
    avg_kernel<<<NB, 1024>>>(meanv, means, avg);
    gate_kernel<<<NB, 512>>>(avg, visfuse_w, visfuse_b, gv, FEAT);
    gate_kernel<<<NB, 512>>>(avg, semfuse_w, semfuse_b, gs, SEM);

    // 4b) fold gates into per-batch weights (hi only)
    scale_conv_w_kernel<<<dim3((512*512+255)/256, NB), 256>>>(w_ks, FEAT, FEAT, gv,
        wksgh, 512, 512);
    scale_conv_w_kernel<<<dim3((512*SEMP+255)/256, NB), 256>>>(w_ks_sem, SEM, FEAT, gs,
        wkssgh, SEMP, 512);

    // 5) ktot = bw @ (gv*w_ks) + calib @ (gs*w_ks_sem) — single-pass fp16, fused K=512+320
    wmma_gemm3<false><<<dim3(4, 63, NB), 256, SMEMB>>>(
        bwh, wksgh, nullptr, FEAT, sBW, (long long)512*512,
        calh, wkssgh, nullptr, SEMP, sBSM, (long long)512*SEMP,
        NBASE, FEAT, FEAT, sBW, nullptr, ktot, 0,
        nullptr, 0, 0);

    // 6) scores, softmax, attn@v, final proj + residual
    attn_kernel<<<dim3(NBASE/32, NB), 256>>>(ktot, qtot, score_ptr);
    softmax_kernel<<<NB*NWAY, 256>>>(score_ptr, attn);
    av_partial_kernel<<<dim3(NB, 25), 256>>>(attn, v, part);
    av_reduce_kernel<<<256, 256>>>(part, outpre);
    gemm_kernel<<<dim3(8, 2, 1), 256>>>(outpre, fc_w, nullptr, nullptr, 0, support_feat,
                                        out_ptr, NB*NWAY, FEAT, FEAT, 0, 0, 0, 0, 0);
}

// round 17
// speedup vs baseline: 3.8634x; 1.1305x over previous
#include <cuda_runtime.h>
#include <cuda_fp16.h>
#include <mma.h>
#include <math.h>
#include <stdint.h>

using namespace nvcuda;

// ---------------- problem constants ----------------
#define NB   8
#define NWAY 16
#define NBASE 8000
#define FEAT 512
#define SEM  300
#define SEMP 320                  // padded SEM (mult of 64)
#define INV_TEMP (1.0f/22.62741699796952f)

// ---------------- device scratch (no allocs allowed) ----------------
__device__ float g_calib[NB*NBASE*SEM];    // calibrated base_seman (fp32, for means)
__device__ float g_suph[NB*NWAY*SEM];
__device__ float g_supcalib[NB*NWAY*SEM];
__device__ float g_qtot[NB*NWAY*FEAT];
__device__ float g_meanv[NB*32*FEAT];
__device__ float g_means[NB*32*SEM];
__device__ float g_avg[NB*(FEAT+SEM)];
__device__ float g_gv[NB*FEAT];
__device__ float g_gs[NB*SEM];
__device__ float g_attn[NB*NWAY*NBASE];
__device__ float g_part[NB*25*NWAY*FEAT];
__device__ float g_outpre[NB*NWAY*FEAT];
__device__ float g_score_scratch[NB*NWAY*NBASE];
__device__ float g_out_scratch[NB*NWAY*FEAT];

// fp16 key/value tensors (GEMM outputs, attention inputs)
__device__ __align__(256) __half g_ktot_h[NB*NBASE*FEAT];
__device__ __align__(256) __half g_v_h[NB*NBASE*FEAT];

// map_sem weights (hi+lo, error-compounding chain), transposed [n, Kp]
__device__ __align__(256) __half g_w1_h[384*SEMP], g_w1_l[384*SEMP];
__device__ __align__(256) __half g_w2_h[384*SEMP], g_w2_l[384*SEMP];
// hi-only weights
__device__ __align__(256) __half g_wvs_h[512*512];
__device__ __align__(256) __half g_wksg_h[NB*512*512];    // per-batch gate-scaled
__device__ __align__(256) __half g_wkssg_h[NB*512*SEMP];  // per-batch gate-scaled

// fp16 activations (hi only), [b, m, Kp]
__device__ __align__(256) __half g_bsm_h[NB*NBASE*SEMP];  // base_seman
__device__ __align__(256) __half g_h_h[NB*NBASE*SEMP];    // map_sem layer1 out
__device__ __align__(256) __half g_bw_h[NB*NBASE*FEAT];   // base_weights
__device__ __align__(256) __half g_cal_h[NB*NBASE*SEMP];  // calib

__device__ __forceinline__ uint32_t smem_cast(const void* p) {
    uint32_t a;
    asm("{ .reg .u64 t; cvta.to.shared.u64 t, %1; cvt.u32.u64 %0, t; }" : "=r"(a) : "l"(p));
    return a;
}
#define CP16(dst, src) asm volatile("cp.async.cg.shared.global [%0], [%1], 16;" :: "r"(dst), "l"(src))
#define CPCOMMIT()     asm volatile("cp.async.commit_group;")
#define CPWAIT(n)      asm volatile("cp.async.wait_group %0;" :: "n"(n))

// ========== weight prep: transpose + fp16 hi/lo split ==========
__global__ void split_w_kernel(const float* __restrict__ W, int K, int N,
                               __half* __restrict__ Th, __half* __restrict__ Tl,
                               int Kp, int Nr)
{
    long long i = (long long)blockIdx.x*256 + threadIdx.x;
    if (i >= (long long)Nr*Kp) return;
    int n = (int)(i / Kp), k = (int)(i % Kp);
    float v = (k < K && n < N) ? W[(long long)k*N + n] : 0.f;
    __half h = __float2half(v);
    Th[i] = h;
    Tl[i] = __float2half(v - __half2float(h));
}

// ========== weight prep: transpose, fp16 hi only ==========
__global__ void conv_w_kernel(const float* __restrict__ W, int K, int N,
                              __half* __restrict__ Th, int Kp, int Nr)
{
    long long i = (long long)blockIdx.x*256 + threadIdx.x;
    if (i >= (long long)Nr*Kp) return;
    int n = (int)(i / Kp), k = (int)(i % Kp);
    float v = (k < K && n < N) ? W[(long long)k*N + n] : 0.f;
    Th[i] = __float2half(v);
}

// ========== gate-scaled weight prep: W'[b][n][k] = gate[b][k]*W[k][n], hi only ==========
__global__ void scale_conv_w_kernel(const float* __restrict__ W, int K, int N,
                                    const float* __restrict__ gate,
                                    __half* __restrict__ Th, int Kp, int Nr)
{
    int b = blockIdx.y;
    long long i = (long long)blockIdx.x*256 + threadIdx.x;
    if (i >= (long long)Nr*Kp) return;
    int n = (int)(i / Kp), k = (int)(i % Kp);
    float v = (k < K && n < N) ? W[(long long)k*N + n] * gate[(long long)b*K + k] : 0.f;
    Th[(long long)b*Nr*Kp + i] = __float2half(v);
}

// ========== activation converts (division-free) ==========
// FEAT case: one row per block, 64 threads x 8 elems
__global__ void conv_a8_kernel(const float* __restrict__ X, long long sXb,
                               __half* __restrict__ H)
{
    int b = blockIdx.y;
    long long row = blockIdx.x;
    int k = threadIdx.x * 8;
    const float* src = X + (long long)b*sXb + row*FEAT + k;
    float4 v0 = *reinterpret_cast<const float4*>(src);
    float4 v1 = *reinterpret_cast<const float4*>(src + 4);
    __half2 h[4];
    h[0] = __floats2half2_rn(v0.x, v0.y);
    h[1] = __floats2half2_rn(v0.z, v0.w);
    h[2] = __floats2half2_rn(v1.x, v1.y);
    h[3] = __floats2half2_rn(v1.z, v1.w);
    *reinterpret_cast<uint4*>(H + ((long long)b*NBASE + row)*FEAT + k)
        = *reinterpret_cast<uint4*>(h);
}

// SEM case: one row per block, 160 threads x half2 (zero-pad to SEMP)
__global__ void conv_a2_kernel(const float* __restrict__ X, long long sXb,
                               __half* __restrict__ H)
{
    int b = blockIdx.y;
    long long row = blockIdx.x;
    int k = threadIdx.x * 2;
    float a = 0.f, c = 0.f;
    if (k < SEM) {
        const float* src = X + (long long)b*sXb + row*SEM + k;
        a = src[0]; c = src[1];
    }
    *reinterpret_cast<__half2*>(H + ((long long)b*NBASE + row)*SEMP + k)
        = __floats2half2_rn(a, c);
}

// ================= WMMA fp16 GEMM, dual-K-source, cp.async double-buffered ========
// C[b] = act( A1[b] @ B1[b]^T + A2[b] @ B2[b]^T + bias )
// A fp16 [M, Kp]; B fp16 [n, Kp] hi (+lo if USE_LO). KC must divide K1p and K2p.
// Block tile 128x128, 8 warps as 2(m)x4(n), warp tile 64x32, K-chunk KC.
#define LDC 136    // smem epilogue leading dim in f32
template<int KC, bool USE_LO>
__global__ void __launch_bounds__(256, 2) wmma_gemm3(
    const __half* __restrict__ A1, const __half* __restrict__ B1h, const __half* __restrict__ B1l,
    int K1p, long long sA1b, long long sB1b,
    const __half* __restrict__ A2, const __half* __restrict__ B2h, const __half* __restrict__ B2l,
    int K2p, long long sA2b, long long sB2b,
    int Mrows, int N, int Nc, long long sCb,
    const float* __restrict__ bias,
    float* __restrict__ C, int act,
    __half* __restrict__ Ch, long long sCHb, int NcH)
{
    extern __shared__ char smem[];
    const int LDT = KC + 8;
    const int NMAT = USE_LO ? 3 : 2;
    const int STAGE = NMAT*128*LDT;           // halves per stage
    const int SEGROW = KC/8;                  // 16B segs per row
    const int PERTHR = KC/16;                 // segs per thread per matrix
    __half* s0 = (__half*)smem;
    float* sC = (float*)smem;

    int b = blockIdx.z;
    int m0 = blockIdx.y*128, n0 = blockIdx.x*128;
    int tid = threadIdx.x, wid = tid >> 5;
    int wm = (wid & 1)*64, wn = (wid >> 1)*32;

    auto load_chunk = [&](int c, int buf) {
        int k0 = c*KC;
        const __half *Ap, *Bph, *Bpl = nullptr;
        int Kp;
        if (k0 < K1p) {
            Ap  = A1 + (long long)b*sA1b + k0;
            Bph = B1h + (long long)b*sB1b + k0;
            if (USE_LO) Bpl = B1l + (long long)b*sB1b + k0;
            Kp = K1p;
        } else {
            int k2 = k0 - K1p;
            Ap  = A2 + (long long)b*sA2b + k2;
            Bph = B2h + (long long)b*sB2b + k2;
            if (USE_LO) Bpl = B2l + (long long)b*sB2b + k2;
            Kp = K2p;
        }
        __half* st = s0 + buf*STAGE;
        #pragma unroll
        for (int s = 0; s < PERTHR; s++) {
            int idx = tid + s*256;
            int row = idx / SEGROW, q = idx % SEGROW;    // SEGROW is power of 2
            int am = m0 + row; if (am >= Mrows) am = Mrows - 1;
            CP16(smem_cast(&st[row*LDT + q*8]), Ap + (long long)am*Kp + q*8);
            CP16(smem_cast(&st[128*LDT + row*LDT + q*8]), Bph + (long long)(n0+row)*Kp + q*8);
            if (USE_LO)
                CP16(smem_cast(&st[2*128*LDT + row*LDT + q*8]), Bpl + (long long)(n0+row)*Kp + q*8);
        }
    };

    wmma::fragment<wmma::accumulator, 16, 16, 16, float> acc[4][2];
    #pragma unroll
    for (int i = 0; i < 4; i++)
        #pragma unroll
        for (int j = 0; j < 2; j++) wmma::fill_fragment(acc[i][j], 0.f);

    const int nc = (K1p + K2p)/KC;
    load_chunk(0, 0);
    CPCOMMIT();
    for (int c = 0; c < nc; c++) {
        int buf = c & 1;
        CPWAIT(0);
        __syncthreads();
        if (c+1 < nc) { load_chunk(c+1, buf ^ 1); CPCOMMIT(); }
        __half* st = s0 + buf*STAGE;
        __half* sA  = st;
        __half* sBh = st + 128*LDT;
        __half* sBl = st + 2*128*LDT;
        #pragma unroll
        for (int ks = 0; ks < KC/16; ks++) {
            wmma::fragment<wmma::matrix_a, 16, 16, 16, __half, wmma::row_major> af[4];
            wmma::fragment<wmma::matrix_b, 16, 16, 16, __half, wmma::col_major> bh[2];
            #pragma unroll
            for (int i = 0; i < 4; i++)
                wmma::load_matrix_sync(af[i], &sA[(wm + i*16)*LDT + ks*16], LDT);
            #pragma unroll
            for (int j = 0; j < 2; j++)
                wmma::load_matrix_sync(bh[j], &sBh[(wn + j*16)*LDT + ks*16], LDT);
            #pragma unroll
            for (int i = 0; i < 4; i++)
                #pragma unroll
                for (int j = 0; j < 2; j++)
                    wmma::mma_sync(acc[i][j], af[i], bh[j], acc[i][j]);
            if (USE_LO) {
                wmma::fragment<wmma::matrix_b, 16, 16, 16, __half, wmma::col_major> bl[2];
                #pragma unroll
                for (int j = 0; j < 2; j++)
                    wmma::load_matrix_sync(bl[j], &sBl[(wn + j*16)*LDT + ks*16], LDT);
                #pragma unroll
                for (int i = 0; i < 4; i++)
                    #pragma unroll
                    for (int j = 0; j < 2; j++)
                        wmma::mma_sync(acc[i][j], af[i], bl[j], acc[i][j]);
            }
        }
        __syncthreads();   // all warps done with buf before it is reloaded (chunk c+2)
    }

    // ---- epilogue: frags -> smem -> outputs ----
    #pragma unroll
    for (int i = 0; i < 4; i++)
        #pragma unroll
        for (int j = 0; j < 2; j++)
            wmma::store_matrix_sync(&sC[(wm + i*16)*LDC + wn + j*16], acc[i][j], LDC,
                                    wmma::mem_row_major);
    __syncthreads();
    float* Cb = C ? C + (long long)b*sCb : nullptr;
    for (int j = 0; j < 64; j++) {
        int lin = tid + j*256;                // 16384 = 128x128
        int row = lin >> 7, col = lin & 127;
        int gm = m0 + row, gn = n0 + col;
        if (gm >= Mrows) continue;
        float v = 0.f;
        if (gn < N) {
            v = sC[row*LDC + col];
            if (bias) v += bias[gn];
            if (act)  v = (v >= 0.f) ? v : 0.1f*v;
            if (Cb) Cb[(long long)gm*Nc + gn] = v;
        }
        if (Ch && gn < NcH)
            Ch[sCHb*b + (long long)gm*NcH + gn] = __float2half(v);
    }
}

// ---------------- fp32 tiled GEMM (small matrices only) ----------------
#define BM 64
#define BN 64
#define BK 16
__global__ void gemm_kernel(const float* __restrict__ A, const float* __restrict__ B,
                            const float* __restrict__ bias,
                            const float* __restrict__ gate, int gateK,
                            const float* __restrict__ resid,
                            float* __restrict__ C,
                            int M, int K, int N,
                            long long sAb, long long sBb, long long sCb,
                            int act, int accum)
{
    int b = blockIdx.z;
    A += (long long)b * sAb;
    B += (long long)b * sBb;
    C += (long long)b * sCb;
    const float* gt = gate ? (gate + (long long)b * gateK) : nullptr;

    __shared__ float As[BK][BM+1];
    __shared__ float Bs[BK][BN+1];

    int tid = threadIdx.x;
    int tx = tid & 15, ty = tid >> 4;
    int m0 = blockIdx.y * BM, n0 = blockIdx.x * BN;

    float acc[4][4];
    #pragma unroll
    for (int i = 0; i < 4; i++)
        #pragma unroll
        for (int j = 0; j < 4; j++) acc[i][j] = 0.f;

    for (int k0 = 0; k0 < K; k0 += BK) {
        #pragma unroll
        for (int l = 0; l < 4; l++) {
            int i = tid + l*256;
            int ar = i >> 4, ac = i & 15;
            int gm = m0 + ar, gk = k0 + ac;
            float vv = 0.f;
            if (gm < M && gk < K) {
                vv = A[(long long)gm*K + gk];
                if (gt) vv *= gt[gk];
            }
            As[ac][ar] = vv;
        }
        #pragma unroll
        for (int l = 0; l < 4; l++) {
            int i = tid + l*256;
            int br = i >> 6, bc = i & 63;
            int gk = k0 + br, gn = n0 + bc;
            Bs[br][bc] = (gk < K && gn < N) ? B[(long long)gk*N + gn] : 0.f;
        }
        __syncthreads();
        #pragma unroll
        for (int kk = 0; kk < BK; kk++) {
            float a[4], bb[4];
            #pragma unroll
            for (int i = 0; i < 4; i++) a[i] = As[kk][ty*4+i];
            #pragma unroll
            for (int j = 0; j < 4; j++) bb[j] = Bs[kk][tx*4+j];
            #pragma unroll
            for (int i = 0; i < 4; i++)
                #pragma unroll
                for (int j = 0; j < 4; j++)
                    acc[i][j] += a[i]*bb[j];
        }
        __syncthreads();
    }

    #pragma unroll
    for (int i = 0; i < 4; i++) {
        int gm = m0 + ty*4 + i;
        if (gm >= M) continue;
        #pragma unroll
        for (int j = 0; j < 4; j++) {
            int gn = n0 + tx*4 + j;
            if (gn >= N) continue;
            float vv = acc[i][j];
            if (bias) vv += bias[gn];
            if (act == 1) vv = (vv >= 0.f) ? vv : 0.1f*vv;
            if (resid) vv += resid[(long long)gm*N + gn];
            long long idx = (long long)gm*N + gn;
            if (accum) vv += C[idx];
            C[idx] = vv;
        }
    }
}

// ---------------- column means (partial over 250-row chunks) ----------------
__global__ void mean_part_kernel(const float* __restrict__ X, float* __restrict__ part, int C)
{
    int b = blockIdx.y, ch = blockIdx.x;
    int c = threadIdx.x;
    if (c >= C) return;
    const float* p = X + ((long long)b*NBASE + ch*250)*C + c;
    float s = 0.f;
    for (int r = 0; r < 250; r++) s += p[(long long)r*C];
    part[((long long)b*32 + ch)*C + c] = s;
}

__global__ void avg_kernel(const float* __restrict__ pv, const float* __restrict__ ps,
                           float* __restrict__ avg)
{
    int b = blockIdx.x, c = threadIdx.x;
    if (c < FEAT) {
        float s = 0.f;
        for (int ch = 0; ch < 32; ch++) s += pv[((long long)b*32+ch)*FEAT + c];
        avg[b*(FEAT+SEM) + c] = s * (1.0f/NBASE);
    } else if (c < FEAT + SEM) {
        int cc = c - FEAT;
        float s = 0.f;
        for (int ch = 0; ch < 32; ch++) s += ps[((long long)b*32+ch)*SEM + cc];
        avg[b*(FEAT+SEM) + FEAT + cc] = s * (1.0f/NBASE);
    }
}

__global__ void gate_kernel(const float* __restrict__ avg, const float* __restrict__ W,
                            const float* __restrict__ bias, float* __restrict__ gate, int N)
{
    int b = blockIdx.x, j = threadIdx.x;
    __shared__ float av[FEAT+SEM];
    for (int i = threadIdx.x; i < FEAT+SEM; i += blockDim.x) av[i] = avg[b*(FEAT+SEM) + i];
    __syncthreads();
    if (j < N) {
        float s = bias[j];
        for (int k = 0; k < FEAT+SEM; k++) s += av[k]*W[(long long)k*N + j];
        gate[b*N + j] = 1.f + 1.f/(1.f + expf(-s));
    }
}

// ---------------- attention scores (fp16 keys) ----------------
__global__ void attn_kernel(const __half* __restrict__ ktot, const float* __restrict__ qtot,
                            float* __restrict__ score)
{
    int b = blockIdx.y;
    int n0 = blockIdx.x * 32;
    __shared__ float qs[NWAY][FEAT];
    __shared__ float ks[32][33];
    const float* q = qtot + (long long)b*NWAY*FEAT;
    for (int i = threadIdx.x; i < NWAY*FEAT; i += 256) qs[i>>9][i&511] = q[i];
    int r  = threadIdx.x & 31;
    int wg = threadIdx.x >> 5;
    float acc0 = 0.f, acc1 = 0.f;
    const __half* kb = ktot + ((long long)b*NBASE + n0)*FEAT;
    for (int k0 = 0; k0 < FEAT; k0 += 32) {
        __syncthreads();
        for (int i = threadIdx.x; i < 32*16; i += 256) {      // half2 units
            int rr = i >> 4, c2 = i & 15;
            __half2 hv = *reinterpret_cast<const __half2*>(kb + (long long)rr*FEAT + k0 + c2*2);
            float2 f = __half22float2(hv);
            ks[rr][c2*2]   = f.x;
            ks[rr][c2*2+1] = f.y;
        }
        __syncthreads();
        #pragma unroll
        for (int kk = 0; kk < 32; kk++) {
            float kv = ks[r][kk];
            acc0 += kv * qs[2*wg  ][k0+kk];
            acc1 += kv * qs[2*wg+1][k0+kk];
        }
    }
    score[((long long)b*NWAY + 2*wg  )*NBASE + n0 + r] = acc0 * INV_TEMP;
    score[((long long)b*NWAY + 2*wg+1)*NBASE + n0 + r] = acc1 * INV_TEMP;
}

// ---------------- softmax ----------------
__global__ void softmax_kernel(const float* __restrict__ score, float* __restrict__ attn)
{
    int row = blockIdx.x;
    const float* s = score + (long long)row*NBASE;
    float* a = attn + (long long)row*NBASE;
    __shared__ float red[256];
    float mx = -1e30f;
    for (int i = threadIdx.x; i < NBASE; i += 256) mx = fmaxf(mx, s[i]);
    red[threadIdx.x] = mx; __syncthreads();
    for (int st = 128; st > 0; st >>= 1) {
        if (threadIdx.x < st) red[threadIdx.x] = fmaxf(red[threadIdx.x], red[threadIdx.x+st]);
        __syncthreads();
    }
    mx = red[0]; __syncthreads();
    float sum = 0.f;
    for (int i = threadIdx.x; i < NBASE; i += 256) {
        float e = expf(s[i] - mx);
        a[i] = e;
        sum += e;
    }
    red[threadIdx.x] = sum; __syncthreads();
    for (int st = 128; st > 0; st >>= 1) {
        if (threadIdx.x < st) red[threadIdx.x] += red[threadIdx.x+st];
        __syncthreads();
    }
    float inv = 1.f/red[0];
    for (int i = threadIdx.x; i < NBASE; i += 256) a[i] *= inv;
}

// ---------------- attn @ v (fp16 values), deterministic split-K ----------------
__global__ void av_partial_kernel(const float* __restrict__ attn, const __half* __restrict__ v,
                                  float* __restrict__ part)
{
    int b  = blockIdx.x;
    int ch = blockIdx.y;
    int n0 = ch * 320;
    __shared__ float as[NWAY][32];
    int c0 = threadIdx.x * 2;     // adjacent column pair
    float acc[NWAY][2];
    #pragma unroll
    for (int w = 0; w < NWAY; w++) { acc[w][0] = 0.f; acc[w][1] = 0.f; }

    for (int nb = 0; nb < 320; nb += 32) {
        __syncthreads();
        for (int i = threadIdx.x; i < NWAY*32; i += 256) {
            int w = i >> 5, nn = i & 31;
            as[w][nn] = attn[((long long)b*NWAY + w)*NBASE + n0 + nb + nn];
        }
        __syncthreads();
        for (int nn = 0; nn < 32; nn++) {
            const __half2 hv = *reinterpret_cast<const __half2*>(
                v + ((long long)b*NBASE + n0 + nb + nn)*FEAT + c0);
            float2 f = __half22float2(hv);
            #pragma unroll
            for (int w = 0; w < NWAY; w++) {
                acc[w][0] += as[w][nn]*f.x;
                acc[w][1] += as[w][nn]*f.y;
            }
        }
    }
    #pragma unroll
    for (int w = 0; w < NWAY; w++) {
        *reinterpret_cast<float2*>(
            &part[(((long long)b*25 + ch)*NWAY + w)*FEAT + c0])
            = make_float2(acc[w][0], acc[w][1]);
    }
}

__global__ void av_reduce_kernel(const float* __restrict__ part, float* __restrict__ outpre)
{
    long long i = (long long)blockIdx.x*256 + threadIdx.x;
    int c = i & 511;
    long long bw = i >> 9;
    int w = bw & 15;
    int b = (int)(bw >> 4);
    float s = 0.f;
    for (int ch = 0; ch < 25; ch++)
        s += part[(((long long)b*25 + ch)*NWAY + w)*FEAT + c];
    outpre[i] = s;
}

// ---------------- host ----------------
extern "C" void kernel_launch(void* const* d_in, const int* in_sizes, int n_in,
                              void* d_out, int out_size)
{
    const float* support_feat  = (const float*)d_in[0];
    const float* base_weights  = (const float*)d_in[1];
    const float* support_seman = (const float*)d_in[2];
    const float* base_seman    = (const float*)d_in[3];
    const float* map_w1 = (const float*)d_in[4];
    const float* map_b1 = (const float*)d_in[5];
    const float* map_w2 = (const float*)d_in[6];
    const float* map_b2 = (const float*)d_in[7];
    const float* visfuse_w = (const float*)d_in[8];
    const float* visfuse_b = (const float*)d_in[9];
    const float* semfuse_w = (const float*)d_in[10];
    const float* semfuse_b = (const float*)d_in[11];
    const float* w_qs = (const float*)d_in[12];
    const float* w_ks = (const float*)d_in[13];
    const float* w_vs = (const float*)d_in[14];
    const float* w_qs_sem = (const float*)d_in[15];
    const float* w_ks_sem = (const float*)d_in[16];
    const float* fc_w = (const float*)d_in[17];

    float *calib, *suph, *supcalib, *qtot;
    float *meanv, *means, *avg, *gv, *gs, *attn, *part, *outpre, *score_sc, *out_sc;
    cudaGetSymbolAddress((void**)&calib, g_calib);
    cudaGetSymbolAddress((void**)&suph, g_suph);
    cudaGetSymbolAddress((void**)&supcalib, g_supcalib);
    cudaGetSymbolAddress((void**)&qtot, g_qtot);
    cudaGetSymbolAddress((void**)&meanv, g_meanv);
    cudaGetSymbolAddress((void**)&means, g_means);
    cudaGetSymbolAddress((void**)&avg, g_avg);
    cudaGetSymbolAddress((void**)&gv, g_gv);
    cudaGetSymbolAddress((void**)&gs, g_gs);
    cudaGetSymbolAddress((void**)&attn, g_attn);
    cudaGetSymbolAddress((void**)&part, g_part);
    cudaGetSymbolAddress((void**)&outpre, g_outpre);
    cudaGetSymbolAddress((void**)&score_sc, g_score_scratch);
    cudaGetSymbolAddress((void**)&out_sc, g_out_scratch);

    __half *ktoth, *vh;
    cudaGetSymbolAddress((void**)&ktoth, g_ktot_h);
    cudaGetSymbolAddress((void**)&vh, g_v_h);

    __half *wvsh, *w1h, *w1l, *w2h, *w2l, *wksgh, *wkssgh;
    cudaGetSymbolAddress((void**)&wvsh, g_wvs_h);
    cudaGetSymbolAddress((void**)&w1h, g_w1_h);       cudaGetSymbolAddress((void**)&w1l, g_w1_l);
    cudaGetSymbolAddress((void**)&w2h, g_w2_h);       cudaGetSymbolAddress((void**)&w2l, g_w2_l);
    cudaGetSymbolAddress((void**)&wksgh, g_wksg_h);
    cudaGetSymbolAddress((void**)&wkssgh, g_wkssg_h);

    __half *bsmh, *hhh, *bwh, *calh;
    cudaGetSymbolAddress((void**)&bsmh, g_bsm_h);
    cudaGetSymbolAddress((void**)&hhh, g_h_h);
    cudaGetSymbolAddress((void**)&bwh, g_bw_h);
    cudaGetSymbolAddress((void**)&calh, g_cal_h);

    // output layout handling: reference returns (out, attn_score)
    const int OUT_N = NB*NWAY*FEAT;
    const int SC_N  = NB*NWAY*NBASE;
    float* out_ptr   = (float*)d_out;
    float* score_ptr = score_sc;
    if (out_size >= OUT_N + SC_N) {
        out_ptr = (float*)d_out;
        score_ptr = (float*)d_out + OUT_N;
    } else if (out_size == SC_N) {
        out_ptr = out_sc;
        score_ptr = (float*)d_out;
    }

    // dynamic smem per instantiation
    const int SMEMB32 = 128*LDC*4;            // 69,632 (maps: 2x30KB stages < epilogue)
    const int SMEMB64 = 2 * 2*128*72*2;       // 73,728 (hi-only KC=64: stages > epilogue)
    cudaFuncSetAttribute(wmma_gemm3<32,true>,  cudaFuncAttributeMaxDynamicSharedMemorySize, SMEMB32);
    cudaFuncSetAttribute(wmma_gemm3<64,false>, cudaFuncAttributeMaxDynamicSharedMemorySize, SMEMB64);

    const long long sBSM = (long long)NBASE*SEMP;
    const long long sBW  = (long long)NBASE*FEAT;

    // 0) weight prep
    conv_w_kernel<<<(512*512+255)/256, 256>>>(w_vs, 512, 512, wvsh, 512, 512);
    split_w_kernel<<<(384*SEMP+255)/256, 256>>>(map_w1, SEM, SEM, w1h, w1l, SEMP, 384);
    split_w_kernel<<<(384*SEMP+255)/256, 256>>>(map_w2, SEM, SEM, w2h, w2l, SEMP, 384);

    // 0b) activation converts (division-free)
    conv_a2_kernel<<<dim3(NBASE, NB), 160>>>(base_seman, (long long)NBASE*SEM, bsmh);
    conv_a8_kernel<<<dim3(NBASE, NB), 64>>>(base_weights, (long long)NBASE*FEAT, bwh);

    // 1) map_sem (hi+lo weights): layer1 -> h fp16 (LeakyReLU), layer2 -> calib fp32 + fp16
    wmma_gemm3<32,true><<<dim3(3, 63, NB), 256, SMEMB32>>>(
        bsmh, w1h, w1l, SEMP, sBSM, 0,
        nullptr, nullptr, nullptr, 0, 0, 0,
        NBASE, SEM, 0, 0, map_b1, nullptr, 1,
        hhh, sBSM, SEMP);
    wmma_gemm3<32,true><<<dim3(3, 63, NB), 256, SMEMB32>>>(
        hhh, w2h, w2l, SEMP, sBSM, 0,
        nullptr, nullptr, nullptr, 0, 0, 0,
        NBASE, SEM, SEM, (long long)NBASE*SEM, map_b2, calib, 0,
        calh, sBSM, SEMP);

    // 2) v = bw @ w_vs (single-pass fp16, KC=64, fp16 output)
    wmma_gemm3<64,false><<<dim3(4, 63, NB), 256, SMEMB64>>>(
        bwh, wvsh, nullptr, FEAT, sBW, 0,
        nullptr, nullptr, nullptr, 0, 0, 0,
        NBASE, FEAT, 0, 0, nullptr, nullptr, 0,
        vh, sBW, FEAT);

    // 3) support-side small fp32 chain (independent)
    gemm_kernel<<<dim3(5, 2, 1), 256>>>(support_seman, map_w1, map_b1, nullptr, 0, nullptr,
                                        suph, NB*NWAY, SEM, SEM, 0, 0, 0, 1, 0);
    gemm_kernel<<<dim3(5, 2, 1), 256>>>(suph, map_w2, map_b2, nullptr, 0, nullptr,
                                        supcalib, NB*NWAY, SEM, SEM, 0, 0, 0, 0, 0);
    gemm_kernel<<<dim3(8, 2, 1), 256>>>(support_feat, w_qs, nullptr, nullptr, 0, nullptr,
                                        qtot, NB*NWAY, FEAT, FEAT, 0, 0, 0, 0, 0);
    gemm_kernel<<<dim3(8, 2, 1), 256>>>(supcalib, w_qs_sem, nullptr, nullptr, 0, nullptr,
                                        qtot, NB*NWAY, SEM, FEAT, 0, 0, 0, 0, 1);

    // 4) means over base classes -> avg -> gates
    mean_part_kernel<<<dim3(32, NB), 512>>>(base_weights, meanv, FEAT);
    mean_part_kernel<<<dim3(32, NB), 512>>>(calib, means, SEM);
    avg_kernel<<<NB, 1024>>>(meanv, means, avg);
    gate_kernel<<<NB, 512>>>(avg, visfuse_w, visfuse_b, gv, FEAT);
    gate_kernel<<<NB, 512>>>(avg, semfuse_w, semfuse_b, gs, SEM);

    // 4b) fold gates into per-batch weights (hi only)
    scale_conv_w_kernel<<<dim3((512*512+255)/256, NB), 256>>>(w_ks, FEAT, FEAT, gv,
        wksgh, 512, 512);
    scale_conv_w_kernel<<<dim3((512*SEMP+255)/256, NB), 256>>>(w_ks_sem, SEM, FEAT, gs,
        wkssgh, SEMP, 512);

    // 5) ktot = bw @ (gv*w_ks) + calib @ (gs*w_ks_sem) — KC=64 fused K=512+320, fp16 out
    wmma_gemm3<64,false><<<dim3(4, 63, NB), 256, SMEMB64>>>(
        bwh, wksgh, nullptr, FEAT, sBW, (long long)512*512,
        calh, wkssgh, nullptr, SEMP, sBSM, (long long)512*SEMP,
        NBASE, FEAT, 0, 0, nullptr, nullptr, 0,
        ktoth, sBW, FEAT);

    // 6) scores, softmax, attn@v, final proj + residual
    attn_kernel<<<dim3(NBASE/32, NB), 256>>>(ktoth, qtot, score_ptr);
    softmax_kernel<<<NB*NWAY, 256>>>(score_ptr, attn);
    av_partial_kernel<<<dim3(NB, 25), 256>>>(attn, vh, part);
    av_reduce_kernel<<<256, 256>>>(part, outpre);
    gemm_kernel<<<dim3(8, 2, 1), 256>>>(outpre, fc_w, nullptr, nullptr, 0, support_feat,
                                        out_ptr, NB*NWAY, FEAT, FEAT, 0, 0, 0, 0, 0);
}